// round 5
// baseline (speedup 1.0000x reference)
#include <cuda_runtime.h>
#include <cuda_bf16.h>
#include <cstddef>
#include <math_constants.h>

#define BB 8
#define CC 512
#define NHEADS 8
#define HD 64
#define NN 1024
#define NGROUPS 32
#define GSIZE ((CC / NGROUPS) * NN)   // 16384
#define EPSV 1e-5f

// ---------------- scratch ----------------
__device__ float g_xn[BB * CC * NN];       // 16 MB
__device__ float g_qkv[BB * 3 * CC * NN];  // 48 MB
__device__ float g_ao[BB * CC * NN];       // 16 MB

// ---------------- async-copy helpers ----------------
__device__ __forceinline__ void cp16(void* sdst, const void* gsrc) {
    unsigned sa = (unsigned)__cvta_generic_to_shared(sdst);
    asm volatile("cp.async.cg.shared.global [%0], [%1], 16;\n" :: "r"(sa), "l"(gsrc));
}
__device__ __forceinline__ void cp_commit() {
    asm volatile("cp.async.commit_group;\n");
}
template <int N>
__device__ __forceinline__ void cp_wait() {
    asm volatile("cp.async.wait_group %0;\n" :: "n"(N));
}

// ---------------- tf32 helpers ----------------
__device__ __forceinline__ unsigned f2tf32(float x) {
    unsigned r;
    asm("cvt.rna.tf32.f32 %0, %1;" : "=r"(r) : "f"(x));
    return r;
}

__device__ __forceinline__ void mma_tf32(float& c0, float& c1, float& c2, float& c3,
                                         unsigned a0, unsigned a1, unsigned a2, unsigned a3,
                                         unsigned b0, unsigned b1) {
    asm volatile(
        "mma.sync.aligned.m16n8k8.row.col.f32.tf32.tf32.f32 "
        "{%0,%1,%2,%3}, {%4,%5,%6,%7}, {%8,%9}, {%0,%1,%2,%3};\n"
        : "+f"(c0), "+f"(c1), "+f"(c2), "+f"(c3)
        : "r"(a0), "r"(a1), "r"(a2), "r"(a3), "r"(b0), "r"(b1));
}

// ---------------- GroupNorm (float4) ----------------
__global__ void groupnorm_kernel(const float* __restrict__ x,
                                 const float* __restrict__ w,
                                 const float* __restrict__ bch,
                                 float* __restrict__ xn) {
    int bg = blockIdx.x;
    const float* xp = x + (size_t)bg * GSIZE;
    float* op = xn + (size_t)bg * GSIZE;
    int t = threadIdx.x;

    float s = 0.f, s2 = 0.f;
    for (int i = t; i < GSIZE / 4; i += blockDim.x) {
        float4 v = *(const float4*)&xp[i * 4];
        s  += v.x + v.y + v.z + v.w;
        s2 += v.x * v.x + v.y * v.y + v.z * v.z + v.w * v.w;
    }
    __shared__ float rs[32], rs2[32];
    for (int o = 16; o; o >>= 1) {
        s  += __shfl_xor_sync(0xffffffffu, s,  o);
        s2 += __shfl_xor_sync(0xffffffffu, s2, o);
    }
    if ((t & 31) == 0) { rs[t >> 5] = s; rs2[t >> 5] = s2; }
    __syncthreads();
    if (t < 32) {
        int nw = blockDim.x >> 5;
        float a  = (t < nw) ? rs[t]  : 0.f;
        float a2 = (t < nw) ? rs2[t] : 0.f;
        for (int o = 16; o; o >>= 1) {
            a  += __shfl_xor_sync(0xffffffffu, a,  o);
            a2 += __shfl_xor_sync(0xffffffffu, a2, o);
        }
        if (t == 0) {
            float mean = a / (float)GSIZE;
            float var  = a2 / (float)GSIZE - mean * mean;
            rs[0]  = mean;
            rs2[0] = rsqrtf(var + EPSV);
        }
    }
    __syncthreads();
    float mean = rs[0], rstd = rs2[0];
    int c0 = (bg % NGROUPS) * (CC / NGROUPS);
    for (int i = t; i < GSIZE / 4; i += blockDim.x) {
        int c = c0 + (i * 4) / NN;
        float sc = rstd * w[c], bc = bch[c] - mean * sc;
        float4 v = *(const float4*)&xp[i * 4];
        v.x = v.x * sc + bc; v.y = v.y * sc + bc;
        v.z = v.z * sc + bc; v.w = v.w * sc + bc;
        *(float4*)&op[i * 4] = v;
    }
}

// ---------------- pipelined tf32 GEMM: C = A[M,K] * B[K,N] (+bias) (+res) ----------------
// tile 128x128x32, 256 threads, 2-stage cp.async pipeline. K multiple of 32.
#define BK 32
#define LDA_S 36
#define LDB_S 132
#define GEMM_STG (128 * LDA_S + BK * LDB_S)          // floats per stage: 8832
#define GEMM_SMEM (2 * GEMM_STG * 4)                 // bytes: 70656

__global__ __launch_bounds__(256)
void mma_gemm(const float* __restrict__ A,
              const float* __restrict__ Bm,
              float* __restrict__ Cm,
              int K, int lda, int ldb, int ldc,
              long long sBi, long long sCi,
              const float* __restrict__ bias,
              const float* __restrict__ res,
              long long sRi) {
    int z = blockIdx.z;
    Bm += z * sBi;
    Cm += z * sCi;
    if (res) res += z * sRi;

    extern __shared__ float smf[];
    float* As[2] = { smf,             smf + GEMM_STG };
    float* Bs[2] = { smf + 128 * LDA_S, smf + GEMM_STG + 128 * LDA_S };

    const int t  = threadIdx.x;
    const int w  = t >> 5, ln = t & 31;
    const int wr = w >> 2, wc = w & 3;
    const int i0 = blockIdx.x * 128, j0 = blockIdx.y * 128;

    // per-thread cp.async indices (4 x float4 each for A and B)
    const int ar = t >> 1, ak = (t & 1) * 16;        // A: rows 0..127 x2 halves, +64 rows
    const int bk = t >> 3, bj = (t & 7) * 16;        // B: k 0..31, j quarters

    auto load_stage = [&](int st, int k0) {
        float* Ad = As[st];
        float* Bd = Bs[st];
#pragma unroll
        for (int h = 0; h < 2; h++) {
            int row = ar + h * 64;  // wait: ar in 0..127 already covers; use 2 quarters of k instead
        }
        // A tile: 128 rows x 32 k. 1024 float4s; thread does 4.
#pragma unroll
        for (int r4 = 0; r4 < 4; r4++) {
            int idx = t + 256 * r4;          // 0..1023
            int row = idx >> 3, kq = (idx & 7) * 4;
            cp16(&Ad[row * LDA_S + kq], &A[(size_t)(i0 + row) * lda + k0 + kq]);
        }
        // B tile: 32 k x 128 j. 1024 float4s; thread does 4.
#pragma unroll
        for (int r4 = 0; r4 < 4; r4++) {
            int idx = t + 256 * r4;
            int k = idx >> 5, jq = (idx & 31) * 4;
            cp16(&Bd[k * LDB_S + jq], &Bm[(size_t)(k0 + k) * ldb + j0 + jq]);
        }
    };

    float acc[4][4][4];
#pragma unroll
    for (int a = 0; a < 4; a++)
#pragma unroll
        for (int b = 0; b < 4; b++)
#pragma unroll
            for (int c = 0; c < 4; c++) acc[a][b][c] = 0.f;

    const int nIter = K / BK;
    load_stage(0, 0);
    cp_commit();

    for (int it = 0; it < nIter; it++) {
        if (it + 1 < nIter) {
            load_stage((it + 1) & 1, (it + 1) * BK);
            cp_commit();
            cp_wait<1>();
        } else {
            cp_wait<0>();
        }
        __syncthreads();
        const float* Ac = As[it & 1];
        const float* Bc = Bs[it & 1];

#pragma unroll
        for (int ks = 0; ks < 4; ks++) {
            int kk = ks * 8;
            unsigned af[4][4];
            unsigned bf[4][2];
#pragma unroll
            for (int mi = 0; mi < 4; mi++) {
                int mR = wr * 64 + mi * 16 + (ln >> 2);
                int ca = kk + (ln & 3);
                af[mi][0] = f2tf32(Ac[mR * LDA_S + ca]);
                af[mi][1] = f2tf32(Ac[(mR + 8) * LDA_S + ca]);
                af[mi][2] = f2tf32(Ac[mR * LDA_S + ca + 4]);
                af[mi][3] = f2tf32(Ac[(mR + 8) * LDA_S + ca + 4]);
            }
#pragma unroll
            for (int ni = 0; ni < 4; ni++) {
                int nB = wc * 32 + ni * 8 + (ln >> 2);
                int kb = kk + (ln & 3);
                bf[ni][0] = f2tf32(Bc[kb * LDB_S + nB]);
                bf[ni][1] = f2tf32(Bc[(kb + 4) * LDB_S + nB]);
            }
#pragma unroll
            for (int mi = 0; mi < 4; mi++)
#pragma unroll
                for (int ni = 0; ni < 4; ni++)
                    mma_tf32(acc[mi][ni][0], acc[mi][ni][1], acc[mi][ni][2], acc[mi][ni][3],
                             af[mi][0], af[mi][1], af[mi][2], af[mi][3],
                             bf[ni][0], bf[ni][1]);
        }
        __syncthreads();
    }

#pragma unroll
    for (int mi = 0; mi < 4; mi++) {
        int r0 = i0 + wr * 64 + mi * 16 + (ln >> 2);
        int r1 = r0 + 8;
        float bv0 = bias ? bias[r0] : 0.f;
        float bv1 = bias ? bias[r1] : 0.f;
#pragma unroll
        for (int ni = 0; ni < 4; ni++) {
            int c0 = j0 + wc * 32 + ni * 8 + 2 * (ln & 3);
            float v00 = acc[mi][ni][0] + bv0;
            float v01 = acc[mi][ni][1] + bv0;
            float v10 = acc[mi][ni][2] + bv1;
            float v11 = acc[mi][ni][3] + bv1;
            if (res) {
                float2 r0v = *(const float2*)&res[(size_t)r0 * ldc + c0];
                float2 r1v = *(const float2*)&res[(size_t)r1 * ldc + c0];
                v00 += r0v.x; v01 += r0v.y;
                v10 += r1v.x; v11 += r1v.y;
            }
            *(float2*)&Cm[(size_t)r0 * ldc + c0] = make_float2(v00, v01);
            *(float2*)&Cm[(size_t)r1 * ldc + c0] = make_float2(v10, v11);
        }
    }
}

// ---------------- fused flash attention (2-stage cp.async K/V pipeline) ----------------
#define QT 128
#define MT 64
#define QS_LD 68
#define KS_LD 72
#define VS_LD 68
#define FA_Q (QT * QS_LD)                       // 8704 words (tf32)
#define FA_K (HD * KS_LD)                       // 4608 words (f32)
#define FA_V (HD * VS_LD)                       // 4352 words
#define FA_SMEM ((FA_Q + 2 * (FA_K + FA_V)) * 4)  // 106496 B

__global__ __launch_bounds__(256)
void flash_attn(const float* __restrict__ qkv, float* __restrict__ ao) {
    extern __shared__ unsigned sm[];
    unsigned* Qs = sm;
    float* Ks[2] = { (float*)(sm + FA_Q),        (float*)(sm + FA_Q + FA_K) };
    float* Vs[2] = { (float*)(sm + FA_Q + 2*FA_K), (float*)(sm + FA_Q + 2*FA_K + FA_V) };

    const int t = threadIdx.x;
    const int w = t >> 5, ln = t & 31;
    const int r = ln >> 2, j = ln & 3;
    const int bh = blockIdx.y;
    const int b = bh >> 3, h = bh & 7;
    const int q0 = blockIdx.x * QT;
    const int qrow = w * 16 + r;

    const float* Qp = qkv + (size_t)b * 3 * CC * NN + (size_t)h * HD * NN;
    const float* Kp = Qp + (size_t)CC * NN;
    const float* Vp = Qp + 2 * (size_t)CC * NN;

    // per-thread K/V copy indices: 1024 float4s each, 4 per thread
    auto load_kv = [&](int st, int mo) {
#pragma unroll
        for (int r4 = 0; r4 < 4; r4++) {
            int idx = t + 256 * r4;
            int c = idx >> 4, mq = (idx & 15) * 4;
            cp16(&Ks[st][c * KS_LD + mq], &Kp[(size_t)c * NN + mo + mq]);
            cp16(&Vs[st][c * VS_LD + mq], &Vp[(size_t)c * NN + mo + mq]);
        }
    };

    load_kv(0, 0);
    cp_commit();

    // load Q tile -> Qs[q][c] (tf32), overlapped with first K/V cp.async
    for (int idx = t; idx < QT * HD; idx += 256) {
        int q = idx & (QT - 1), c = idx >> 7;
        Qs[q * QS_LD + c] = f2tf32(Qp[(size_t)c * NN + q0 + q]);
    }

    float o[8][4];
#pragma unroll
    for (int a = 0; a < 8; a++)
#pragma unroll
        for (int bq = 0; bq < 4; bq++) o[a][bq] = 0.f;
    float m0v = -CUDART_INF_F, m1v = -CUDART_INF_F;
    float l0 = 0.f, l1 = 0.f;

    const int src0 = (ln & ~3) | (j >> 1);
    const int src1 = src0 + 2;
    const int nIt = NN / MT;

    for (int it = 0; it < nIt; it++) {
        if (it + 1 < nIt) {
            load_kv((it + 1) & 1, (it + 1) * MT);
            cp_commit();
            cp_wait<1>();
        } else {
            cp_wait<0>();
        }
        __syncthreads();
        const float* Kc = Ks[it & 1];
        const float* Vc = Vs[it & 1];

        // ---- S = Q^T K ----
        float s[8][4];
#pragma unroll
        for (int a = 0; a < 8; a++)
#pragma unroll
            for (int bq = 0; bq < 4; bq++) s[a][bq] = 0.f;

#pragma unroll
        for (int kf = 0; kf < 8; kf++) {
            int ca = kf * 8 + j;
            unsigned a0 = Qs[qrow * QS_LD + ca];
            unsigned a1 = Qs[(qrow + 8) * QS_LD + ca];
            unsigned a2 = Qs[qrow * QS_LD + ca + 4];
            unsigned a3 = Qs[(qrow + 8) * QS_LD + ca + 4];
#pragma unroll
            for (int ni = 0; ni < 8; ni++) {
                unsigned b0 = f2tf32(Kc[ca * KS_LD + ni * 8 + r]);
                unsigned b1 = f2tf32(Kc[(ca + 4) * KS_LD + ni * 8 + r]);
                mma_tf32(s[ni][0], s[ni][1], s[ni][2], s[ni][3], a0, a1, a2, a3, b0, b1);
            }
        }

        // ---- online softmax ----
        float tm0 = -CUDART_INF_F, tm1 = -CUDART_INF_F;
#pragma unroll
        for (int ni = 0; ni < 8; ni++) {
            s[ni][0] *= 0.125f; s[ni][1] *= 0.125f;
            s[ni][2] *= 0.125f; s[ni][3] *= 0.125f;
            tm0 = fmaxf(tm0, fmaxf(s[ni][0], s[ni][1]));
            tm1 = fmaxf(tm1, fmaxf(s[ni][2], s[ni][3]));
        }
        tm0 = fmaxf(tm0, __shfl_xor_sync(0xffffffffu, tm0, 1));
        tm0 = fmaxf(tm0, __shfl_xor_sync(0xffffffffu, tm0, 2));
        tm1 = fmaxf(tm1, __shfl_xor_sync(0xffffffffu, tm1, 1));
        tm1 = fmaxf(tm1, __shfl_xor_sync(0xffffffffu, tm1, 2));

        float mn0 = fmaxf(m0v, tm0), mn1 = fmaxf(m1v, tm1);
        float al0 = __expf(m0v - mn0), al1 = __expf(m1v - mn1);
        m0v = mn0; m1v = mn1;

        float rs0 = 0.f, rs1 = 0.f;
#pragma unroll
        for (int ni = 0; ni < 8; ni++) {
            s[ni][0] = __expf(s[ni][0] - mn0);
            s[ni][1] = __expf(s[ni][1] - mn0);
            s[ni][2] = __expf(s[ni][2] - mn1);
            s[ni][3] = __expf(s[ni][3] - mn1);
            rs0 += s[ni][0] + s[ni][1];
            rs1 += s[ni][2] + s[ni][3];
        }
        rs0 += __shfl_xor_sync(0xffffffffu, rs0, 1);
        rs0 += __shfl_xor_sync(0xffffffffu, rs0, 2);
        rs1 += __shfl_xor_sync(0xffffffffu, rs1, 1);
        rs1 += __shfl_xor_sync(0xffffffffu, rs1, 2);
        l0 = l0 * al0 + rs0;
        l1 = l1 * al1 + rs1;

#pragma unroll
        for (int no = 0; no < 8; no++) {
            o[no][0] *= al0; o[no][1] *= al0;
            o[no][2] *= al1; o[no][3] *= al1;
        }

        // ---- O += P * V^T ----
#pragma unroll
        for (int km = 0; km < 8; km++) {
            float q00 = __shfl_sync(0xffffffffu, s[km][0], src0);
            float q01 = __shfl_sync(0xffffffffu, s[km][1], src0);
            float q10 = __shfl_sync(0xffffffffu, s[km][0], src1);
            float q11 = __shfl_sync(0xffffffffu, s[km][1], src1);
            float q20 = __shfl_sync(0xffffffffu, s[km][2], src0);
            float q21 = __shfl_sync(0xffffffffu, s[km][3], src0);
            float q30 = __shfl_sync(0xffffffffu, s[km][2], src1);
            float q31 = __shfl_sync(0xffffffffu, s[km][3], src1);
            unsigned pa0 = f2tf32((j & 1) ? q01 : q00);
            unsigned pa2 = f2tf32((j & 1) ? q11 : q10);
            unsigned pa1 = f2tf32((j & 1) ? q21 : q20);
            unsigned pa3 = f2tf32((j & 1) ? q31 : q30);
#pragma unroll
            for (int no = 0; no < 8; no++) {
                unsigned b0 = f2tf32(Vc[(no * 8 + r) * VS_LD + km * 8 + j]);
                unsigned b1 = f2tf32(Vc[(no * 8 + r) * VS_LD + km * 8 + j + 4]);
                mma_tf32(o[no][0], o[no][1], o[no][2], o[no][3], pa0, pa1, pa2, pa3, b0, b1);
            }
        }
        __syncthreads();
    }

    // ---- epilogue ----
    float inv0 = 1.f / l0, inv1 = 1.f / l1;
    float* aop = ao + (size_t)b * CC * NN + (size_t)h * HD * NN;
#pragma unroll
    for (int no = 0; no < 8; no++) {
        int hd0 = no * 8 + 2 * j;
        aop[(size_t)hd0 * NN + q0 + qrow]           = o[no][0] * inv0;
        aop[(size_t)(hd0 + 1) * NN + q0 + qrow]     = o[no][1] * inv0;
        aop[(size_t)hd0 * NN + q0 + qrow + 8]       = o[no][2] * inv1;
        aop[(size_t)(hd0 + 1) * NN + q0 + qrow + 8] = o[no][3] * inv1;
    }
}

// ---------------- launch ----------------
extern "C" void kernel_launch(void* const* d_in, const int* in_sizes, int n_in,
                              void* d_out, int out_size) {
    (void)in_sizes; (void)n_in; (void)out_size;
    const float* x  = (const float*)d_in[0];
    const float* nw = (const float*)d_in[1];
    const float* nb = (const float*)d_in[2];
    const float* qw = (const float*)d_in[3];
    const float* qb = (const float*)d_in[4];
    const float* pw = (const float*)d_in[5];
    const float* pb = (const float*)d_in[6];
    float* out = (float*)d_out;

    float *xn, *qkv, *ao;
    cudaGetSymbolAddress((void**)&xn,  g_xn);
    cudaGetSymbolAddress((void**)&qkv, g_qkv);
    cudaGetSymbolAddress((void**)&ao,  g_ao);

    const long long bCN  = (long long)CC * NN;
    const long long b3CN = 3LL * CC * NN;

    cudaFuncSetAttribute(mma_gemm,  cudaFuncAttributeMaxDynamicSharedMemorySize, GEMM_SMEM);
    cudaFuncSetAttribute(flash_attn, cudaFuncAttributeMaxDynamicSharedMemorySize, FA_SMEM);

    // 1) GroupNorm
    groupnorm_kernel<<<BB * NGROUPS, 256>>>(x, nw, nb, xn);

    // 2) QKV: qkv[b] = qkv_w [1536,512] * xn[b] [512,1024] + qkv_b
    mma_gemm<<<dim3(12, 8, BB), 256, GEMM_SMEM>>>(
        qw, xn, qkv, CC, CC, NN, NN, bCN, b3CN, qb, nullptr, 0);

    // 3) Fused attention
    flash_attn<<<dim3(NN / QT, BB * NHEADS), 256, FA_SMEM>>>(qkv, ao);

    // 4) Proj + bias + residual
    mma_gemm<<<dim3(4, 8, BB), 256, GEMM_SMEM>>>(
        pw, ao, out, CC, CC, NN, NN, bCN, bCN, pb, x, bCN);
}

// round 6
// speedup vs baseline: 1.4136x; 1.4136x over previous
#include <cuda_runtime.h>
#include <cuda_bf16.h>
#include <cstddef>
#include <math_constants.h>

#define BB 8
#define CC 512
#define NHEADS 8
#define HD 64
#define NN 1024
#define NGROUPS 32
#define GSIZE ((CC / NGROUPS) * NN)   // 16384
#define EPSV 1e-5f

// ---------------- scratch ----------------
__device__ float g_xn[BB * CC * NN];       // 16 MB
__device__ float g_qkv[BB * 3 * CC * NN];  // 48 MB
__device__ float g_ao[BB * CC * NN];       // 16 MB

// ---------------- async-copy helpers ----------------
__device__ __forceinline__ void cp16(void* sdst, const void* gsrc) {
    unsigned sa = (unsigned)__cvta_generic_to_shared(sdst);
    asm volatile("cp.async.cg.shared.global [%0], [%1], 16;\n" :: "r"(sa), "l"(gsrc));
}
__device__ __forceinline__ void cp_commit() {
    asm volatile("cp.async.commit_group;\n");
}
template <int N>
__device__ __forceinline__ void cp_wait() {
    asm volatile("cp.async.wait_group %0;\n" :: "n"(N));
}

// ---------------- tf32 helpers ----------------
// NOTE: tf32 MMA truncates the low 13 mantissa bits of whatever bit pattern it
// receives; we feed raw f32 (truncation) instead of cvt.rna (round-to-nearest)
// to keep CVT off the critical path and registers down.
__device__ __forceinline__ unsigned f2tf32(float x) {
    unsigned r;
    asm("cvt.rna.tf32.f32 %0, %1;" : "=r"(r) : "f"(x));
    return r;
}

__device__ __forceinline__ void mma_tf32(float& c0, float& c1, float& c2, float& c3,
                                         unsigned a0, unsigned a1, unsigned a2, unsigned a3,
                                         unsigned b0, unsigned b1) {
    asm volatile(
        "mma.sync.aligned.m16n8k8.row.col.f32.tf32.tf32.f32 "
        "{%0,%1,%2,%3}, {%4,%5,%6,%7}, {%8,%9}, {%0,%1,%2,%3};\n"
        : "+f"(c0), "+f"(c1), "+f"(c2), "+f"(c3)
        : "r"(a0), "r"(a1), "r"(a2), "r"(a3), "r"(b0), "r"(b1));
}

// ---------------- GroupNorm (float4) ----------------
__global__ void groupnorm_kernel(const float* __restrict__ x,
                                 const float* __restrict__ w,
                                 const float* __restrict__ bch,
                                 float* __restrict__ xn) {
    int bg = blockIdx.x;
    const float* xp = x + (size_t)bg * GSIZE;
    float* op = xn + (size_t)bg * GSIZE;
    int t = threadIdx.x;

    float s = 0.f, s2 = 0.f;
    for (int i = t; i < GSIZE / 4; i += blockDim.x) {
        float4 v = *(const float4*)&xp[i * 4];
        s  += v.x + v.y + v.z + v.w;
        s2 += v.x * v.x + v.y * v.y + v.z * v.z + v.w * v.w;
    }
    __shared__ float rs[32], rs2[32];
    for (int o = 16; o; o >>= 1) {
        s  += __shfl_xor_sync(0xffffffffu, s,  o);
        s2 += __shfl_xor_sync(0xffffffffu, s2, o);
    }
    if ((t & 31) == 0) { rs[t >> 5] = s; rs2[t >> 5] = s2; }
    __syncthreads();
    if (t < 32) {
        int nw = blockDim.x >> 5;
        float a  = (t < nw) ? rs[t]  : 0.f;
        float a2 = (t < nw) ? rs2[t] : 0.f;
        for (int o = 16; o; o >>= 1) {
            a  += __shfl_xor_sync(0xffffffffu, a,  o);
            a2 += __shfl_xor_sync(0xffffffffu, a2, o);
        }
        if (t == 0) {
            float mean = a / (float)GSIZE;
            float var  = a2 / (float)GSIZE - mean * mean;
            rs[0]  = mean;
            rs2[0] = rsqrtf(var + EPSV);
        }
    }
    __syncthreads();
    float mean = rs[0], rstd = rs2[0];
    int c0 = (bg % NGROUPS) * (CC / NGROUPS);
    for (int i = t; i < GSIZE / 4; i += blockDim.x) {
        int c = c0 + (i * 4) / NN;
        float sc = rstd * w[c], bc = bch[c] - mean * sc;
        float4 v = *(const float4*)&xp[i * 4];
        v.x = v.x * sc + bc; v.y = v.y * sc + bc;
        v.z = v.z * sc + bc; v.w = v.w * sc + bc;
        *(float4*)&op[i * 4] = v;
    }
}

// ---------------- pipelined tf32 GEMM: C = A[M,K] * B[K,N] (+bias) (+res) ----------------
// tile 128x128x32, 256 threads, 2-stage cp.async pipeline, raw-f32 fragments.
#define BK 32
#define LDA_S 36
#define LDB_S 132
#define GEMM_STG (128 * LDA_S + BK * LDB_S)          // floats per stage: 8832
#define GEMM_SMEM (2 * GEMM_STG * 4)                 // bytes: 70656

__global__ __launch_bounds__(256, 2)
void mma_gemm(const float* __restrict__ A,
              const float* __restrict__ Bm,
              float* __restrict__ Cm,
              int K, int lda, int ldb, int ldc,
              long long sBi, long long sCi,
              const float* __restrict__ bias,
              const float* __restrict__ res,
              long long sRi) {
    int z = blockIdx.z;
    Bm += z * sBi;
    Cm += z * sCi;
    if (res) res += z * sRi;

    extern __shared__ float smf[];
    float* As[2] = { smf,               smf + GEMM_STG };
    float* Bs[2] = { smf + 128 * LDA_S, smf + GEMM_STG + 128 * LDA_S };

    const int t  = threadIdx.x;
    const int w  = t >> 5, ln = t & 31;
    const int wr = w >> 2, wc = w & 3;
    const int i0 = blockIdx.x * 128, j0 = blockIdx.y * 128;

    auto load_stage = [&](int st, int k0) {
        float* Ad = As[st];
        float* Bd = Bs[st];
#pragma unroll
        for (int r4 = 0; r4 < 4; r4++) {
            int idx = t + 256 * r4;          // 0..1023
            int row = idx >> 3, kq = (idx & 7) * 4;
            cp16(&Ad[row * LDA_S + kq], &A[(size_t)(i0 + row) * lda + k0 + kq]);
        }
#pragma unroll
        for (int r4 = 0; r4 < 4; r4++) {
            int idx = t + 256 * r4;
            int k = idx >> 5, jq = (idx & 31) * 4;
            cp16(&Bd[k * LDB_S + jq], &Bm[(size_t)(k0 + k) * ldb + j0 + jq]);
        }
    };

    float acc[4][4][4];
#pragma unroll
    for (int a = 0; a < 4; a++)
#pragma unroll
        for (int b = 0; b < 4; b++)
#pragma unroll
            for (int c = 0; c < 4; c++) acc[a][b][c] = 0.f;

    const int nIter = K / BK;
    load_stage(0, 0);
    cp_commit();

    for (int it = 0; it < nIter; it++) {
        if (it + 1 < nIter) {
            load_stage((it + 1) & 1, (it + 1) * BK);
            cp_commit();
            cp_wait<1>();
        } else {
            cp_wait<0>();
        }
        __syncthreads();
        const unsigned* Ac = (const unsigned*)As[it & 1];
        const unsigned* Bc = (const unsigned*)Bs[it & 1];

#pragma unroll
        for (int ks = 0; ks < 4; ks++) {
            int kk = ks * 8;
            unsigned af[4][4];
            unsigned bf[4][2];
#pragma unroll
            for (int mi = 0; mi < 4; mi++) {
                int mR = wr * 64 + mi * 16 + (ln >> 2);
                int ca = kk + (ln & 3);
                af[mi][0] = Ac[mR * LDA_S + ca];
                af[mi][1] = Ac[(mR + 8) * LDA_S + ca];
                af[mi][2] = Ac[mR * LDA_S + ca + 4];
                af[mi][3] = Ac[(mR + 8) * LDA_S + ca + 4];
            }
#pragma unroll
            for (int ni = 0; ni < 4; ni++) {
                int nB = wc * 32 + ni * 8 + (ln >> 2);
                int kb = kk + (ln & 3);
                bf[ni][0] = Bc[kb * LDB_S + nB];
                bf[ni][1] = Bc[(kb + 4) * LDB_S + nB];
            }
#pragma unroll
            for (int mi = 0; mi < 4; mi++)
#pragma unroll
                for (int ni = 0; ni < 4; ni++)
                    mma_tf32(acc[mi][ni][0], acc[mi][ni][1], acc[mi][ni][2], acc[mi][ni][3],
                             af[mi][0], af[mi][1], af[mi][2], af[mi][3],
                             bf[ni][0], bf[ni][1]);
        }
        __syncthreads();
    }

#pragma unroll
    for (int mi = 0; mi < 4; mi++) {
        int r0 = i0 + wr * 64 + mi * 16 + (ln >> 2);
        int r1 = r0 + 8;
        float bv0 = bias ? bias[r0] : 0.f;
        float bv1 = bias ? bias[r1] : 0.f;
#pragma unroll
        for (int ni = 0; ni < 4; ni++) {
            int c0 = j0 + wc * 32 + ni * 8 + 2 * (ln & 3);
            float v00 = acc[mi][ni][0] + bv0;
            float v01 = acc[mi][ni][1] + bv0;
            float v10 = acc[mi][ni][2] + bv1;
            float v11 = acc[mi][ni][3] + bv1;
            if (res) {
                float2 r0v = *(const float2*)&res[(size_t)r0 * ldc + c0];
                float2 r1v = *(const float2*)&res[(size_t)r1 * ldc + c0];
                v00 += r0v.x; v01 += r0v.y;
                v10 += r1v.x; v11 += r1v.y;
            }
            *(float2*)&Cm[(size_t)r0 * ldc + c0] = make_float2(v00, v01);
            *(float2*)&Cm[(size_t)r1 * ldc + c0] = make_float2(v10, v11);
        }
    }
}

// ---------------- fused flash attention (R4 structure, no P cvt) ----------------
#define QT 128
#define MT 64
#define QS_LD 68
#define KS_LD 72
#define VS_LD 68
#define SMEM_U32 (QT * QS_LD + HD * KS_LD + HD * VS_LD)   // 17664 words = 70656 B

__global__ __launch_bounds__(256)
void flash_attn(const float* __restrict__ qkv, float* __restrict__ ao) {
    extern __shared__ unsigned sm[];
    unsigned* Qs = sm;
    unsigned* Ks = sm + QT * QS_LD;
    unsigned* Vs = Ks + HD * KS_LD;

    const int t = threadIdx.x;
    const int w = t >> 5, ln = t & 31;
    const int r = ln >> 2, j = ln & 3;
    const int bh = blockIdx.y;
    const int b = bh >> 3, h = bh & 7;
    const int q0 = blockIdx.x * QT;
    const int qrow = w * 16 + r;

    const float* Qp = qkv + (size_t)b * 3 * CC * NN + (size_t)h * HD * NN;
    const float* Kp = Qp + (size_t)CC * NN;
    const float* Vp = Qp + 2 * (size_t)CC * NN;

    // load Q tile -> Qs[q][c] (raw f32 bits; MMA truncates to tf32)
    for (int idx = t; idx < QT * HD; idx += 256) {
        int q = idx & (QT - 1), c = idx >> 7;
        Qs[q * QS_LD + c] = __float_as_uint(Qp[(size_t)c * NN + q0 + q]);
    }

    float o[8][4];
#pragma unroll
    for (int a = 0; a < 8; a++)
#pragma unroll
        for (int bq = 0; bq < 4; bq++) o[a][bq] = 0.f;
    float m0v = -CUDART_INF_F, m1v = -CUDART_INF_F;
    float l0 = 0.f, l1 = 0.f;

    const int src0 = (ln & ~3) | (j >> 1);
    const int src1 = src0 + 2;

    for (int it = 0; it < NN / MT; it++) {
        int mo = it * MT;
        __syncthreads();
        for (int idx = t; idx < HD * MT / 4; idx += 256) {
            int c = idx >> 4, mq = (idx & 15) * 4;
            float4 kv = *(const float4*)&Kp[(size_t)c * NN + mo + mq];
            *(uint4*)&Ks[c * KS_LD + mq] = *(const uint4*)&kv;
            float4 vv = *(const float4*)&Vp[(size_t)c * NN + mo + mq];
            *(uint4*)&Vs[c * VS_LD + mq] = *(const uint4*)&vv;
        }
        __syncthreads();

        // ---- S = Q^T K ----
        float s[8][4];
#pragma unroll
        for (int a = 0; a < 8; a++)
#pragma unroll
            for (int bq = 0; bq < 4; bq++) s[a][bq] = 0.f;

#pragma unroll
        for (int kf = 0; kf < 8; kf++) {
            int ca = kf * 8 + j;
            unsigned a0 = Qs[qrow * QS_LD + ca];
            unsigned a1 = Qs[(qrow + 8) * QS_LD + ca];
            unsigned a2 = Qs[qrow * QS_LD + ca + 4];
            unsigned a3 = Qs[(qrow + 8) * QS_LD + ca + 4];
#pragma unroll
            for (int ni = 0; ni < 8; ni++) {
                unsigned b0 = Ks[ca * KS_LD + ni * 8 + r];
                unsigned b1 = Ks[(ca + 4) * KS_LD + ni * 8 + r];
                mma_tf32(s[ni][0], s[ni][1], s[ni][2], s[ni][3], a0, a1, a2, a3, b0, b1);
            }
        }

        // ---- online softmax ----
        float tm0 = -CUDART_INF_F, tm1 = -CUDART_INF_F;
#pragma unroll
        for (int ni = 0; ni < 8; ni++) {
            s[ni][0] *= 0.125f; s[ni][1] *= 0.125f;
            s[ni][2] *= 0.125f; s[ni][3] *= 0.125f;
            tm0 = fmaxf(tm0, fmaxf(s[ni][0], s[ni][1]));
            tm1 = fmaxf(tm1, fmaxf(s[ni][2], s[ni][3]));
        }
        tm0 = fmaxf(tm0, __shfl_xor_sync(0xffffffffu, tm0, 1));
        tm0 = fmaxf(tm0, __shfl_xor_sync(0xffffffffu, tm0, 2));
        tm1 = fmaxf(tm1, __shfl_xor_sync(0xffffffffu, tm1, 1));
        tm1 = fmaxf(tm1, __shfl_xor_sync(0xffffffffu, tm1, 2));

        float mn0 = fmaxf(m0v, tm0), mn1 = fmaxf(m1v, tm1);
        float al0 = __expf(m0v - mn0), al1 = __expf(m1v - mn1);
        m0v = mn0; m1v = mn1;

        float rs0 = 0.f, rs1 = 0.f;
#pragma unroll
        for (int ni = 0; ni < 8; ni++) {
            s[ni][0] = __expf(s[ni][0] - mn0);
            s[ni][1] = __expf(s[ni][1] - mn0);
            s[ni][2] = __expf(s[ni][2] - mn1);
            s[ni][3] = __expf(s[ni][3] - mn1);
            rs0 += s[ni][0] + s[ni][1];
            rs1 += s[ni][2] + s[ni][3];
        }
        rs0 += __shfl_xor_sync(0xffffffffu, rs0, 1);
        rs0 += __shfl_xor_sync(0xffffffffu, rs0, 2);
        rs1 += __shfl_xor_sync(0xffffffffu, rs1, 1);
        rs1 += __shfl_xor_sync(0xffffffffu, rs1, 2);
        l0 = l0 * al0 + rs0;
        l1 = l1 * al1 + rs1;

#pragma unroll
        for (int no = 0; no < 8; no++) {
            o[no][0] *= al0; o[no][1] *= al0;
            o[no][2] *= al1; o[no][3] *= al1;
        }

        // ---- O += P * V^T : C-frag -> A-frag via quad shuffles (raw f32 P) ----
#pragma unroll
        for (int km = 0; km < 8; km++) {
            float q00 = __shfl_sync(0xffffffffu, s[km][0], src0);
            float q01 = __shfl_sync(0xffffffffu, s[km][1], src0);
            float q10 = __shfl_sync(0xffffffffu, s[km][0], src1);
            float q11 = __shfl_sync(0xffffffffu, s[km][1], src1);
            float q20 = __shfl_sync(0xffffffffu, s[km][2], src0);
            float q21 = __shfl_sync(0xffffffffu, s[km][3], src0);
            float q30 = __shfl_sync(0xffffffffu, s[km][2], src1);
            float q31 = __shfl_sync(0xffffffffu, s[km][3], src1);
            unsigned pa0 = __float_as_uint((j & 1) ? q01 : q00);
            unsigned pa2 = __float_as_uint((j & 1) ? q11 : q10);
            unsigned pa1 = __float_as_uint((j & 1) ? q21 : q20);
            unsigned pa3 = __float_as_uint((j & 1) ? q31 : q30);
#pragma unroll
            for (int no = 0; no < 8; no++) {
                unsigned b0 = Vs[(no * 8 + r) * VS_LD + km * 8 + j];
                unsigned b1 = Vs[(no * 8 + r) * VS_LD + km * 8 + j + 4];
                mma_tf32(o[no][0], o[no][1], o[no][2], o[no][3], pa0, pa1, pa2, pa3, b0, b1);
            }
        }
    }

    // ---- epilogue ----
    float inv0 = 1.f / l0, inv1 = 1.f / l1;
    float* aop = ao + (size_t)b * CC * NN + (size_t)h * HD * NN;
#pragma unroll
    for (int no = 0; no < 8; no++) {
        int hd0 = no * 8 + 2 * j;
        aop[(size_t)hd0 * NN + q0 + qrow]           = o[no][0] * inv0;
        aop[(size_t)(hd0 + 1) * NN + q0 + qrow]     = o[no][1] * inv0;
        aop[(size_t)hd0 * NN + q0 + qrow + 8]       = o[no][2] * inv1;
        aop[(size_t)(hd0 + 1) * NN + q0 + qrow + 8] = o[no][3] * inv1;
    }
}

// ---------------- launch ----------------
extern "C" void kernel_launch(void* const* d_in, const int* in_sizes, int n_in,
                              void* d_out, int out_size) {
    (void)in_sizes; (void)n_in; (void)out_size;
    const float* x  = (const float*)d_in[0];
    const float* nw = (const float*)d_in[1];
    const float* nb = (const float*)d_in[2];
    const float* qw = (const float*)d_in[3];
    const float* qb = (const float*)d_in[4];
    const float* pw = (const float*)d_in[5];
    const float* pb = (const float*)d_in[6];
    float* out = (float*)d_out;

    float *xn, *qkv, *ao;
    cudaGetSymbolAddress((void**)&xn,  g_xn);
    cudaGetSymbolAddress((void**)&qkv, g_qkv);
    cudaGetSymbolAddress((void**)&ao,  g_ao);

    const long long bCN  = (long long)CC * NN;
    const long long b3CN = 3LL * CC * NN;

    cudaFuncSetAttribute(mma_gemm,   cudaFuncAttributeMaxDynamicSharedMemorySize, GEMM_SMEM);
    cudaFuncSetAttribute(flash_attn, cudaFuncAttributeMaxDynamicSharedMemorySize, SMEM_U32 * 4);

    // 1) GroupNorm
    groupnorm_kernel<<<BB * NGROUPS, 256>>>(x, nw, nb, xn);

    // 2) QKV: qkv[b] = qkv_w [1536,512] * xn[b] [512,1024] + qkv_b
    mma_gemm<<<dim3(12, 8, BB), 256, GEMM_SMEM>>>(
        qw, xn, qkv, CC, CC, NN, NN, bCN, b3CN, qb, nullptr, 0);

    // 3) Fused attention
    flash_attn<<<dim3(NN / QT, BB * NHEADS), 256, SMEM_U32 * 4>>>(qkv, ao);

    // 4) Proj + bias + residual
    mma_gemm<<<dim3(4, 8, BB), 256, GEMM_SMEM>>>(
        pw, ao, out, CC, CC, NN, NN, bCN, bCN, pb, x, bCN);
}

// round 7
// speedup vs baseline: 1.4927x; 1.0559x over previous
#include <cuda_runtime.h>
#include <cuda_bf16.h>
#include <cstddef>
#include <math_constants.h>

#define BB 8
#define CC 512
#define NHEADS 8
#define HD 64
#define NN 1024
#define NGROUPS 32
#define GSIZE ((CC / NGROUPS) * NN)   // 16384
#define EPSV 1e-5f

// ---------------- scratch ----------------
__device__ float g_xn[BB * CC * NN];       // 16 MB
__device__ float g_qkv[BB * 3 * CC * NN];  // 48 MB
__device__ float g_ao[BB * CC * NN];       // 16 MB

// ---------------- async-copy helpers ----------------
__device__ __forceinline__ void cp16(void* sdst, const void* gsrc) {
    unsigned sa = (unsigned)__cvta_generic_to_shared(sdst);
    asm volatile("cp.async.cg.shared.global [%0], [%1], 16;\n" :: "r"(sa), "l"(gsrc));
}
__device__ __forceinline__ void cp_commit() {
    asm volatile("cp.async.commit_group;\n");
}
template <int N>
__device__ __forceinline__ void cp_wait() {
    asm volatile("cp.async.wait_group %0;\n" :: "n"(N));
}

// ---------------- ldmatrix: 4x (8 rows x 16B) -> 4 regs/thread ----------------
__device__ __forceinline__ void ldsm_x4(unsigned& d0, unsigned& d1,
                                        unsigned& d2, unsigned& d3, const void* p) {
    unsigned sa = (unsigned)__cvta_generic_to_shared(p);
    asm volatile("ldmatrix.sync.aligned.m8n8.x4.shared.b16 {%0,%1,%2,%3}, [%4];\n"
                 : "=r"(d0), "=r"(d1), "=r"(d2), "=r"(d3) : "r"(sa));
}

// ---------------- tf32 mma (raw f32 bits; HW truncates mantissa) ----------------
__device__ __forceinline__ void mma_tf32(float& c0, float& c1, float& c2, float& c3,
                                         unsigned a0, unsigned a1, unsigned a2, unsigned a3,
                                         unsigned b0, unsigned b1) {
    asm volatile(
        "mma.sync.aligned.m16n8k8.row.col.f32.tf32.tf32.f32 "
        "{%0,%1,%2,%3}, {%4,%5,%6,%7}, {%8,%9}, {%0,%1,%2,%3};\n"
        : "+f"(c0), "+f"(c1), "+f"(c2), "+f"(c3)
        : "r"(a0), "r"(a1), "r"(a2), "r"(a3), "r"(b0), "r"(b1));
}

// ---------------- GroupNorm (float4) ----------------
__global__ void groupnorm_kernel(const float* __restrict__ x,
                                 const float* __restrict__ w,
                                 const float* __restrict__ bch,
                                 float* __restrict__ xn) {
    int bg = blockIdx.x;
    const float* xp = x + (size_t)bg * GSIZE;
    float* op = xn + (size_t)bg * GSIZE;
    int t = threadIdx.x;

    float s = 0.f, s2 = 0.f;
    for (int i = t; i < GSIZE / 4; i += blockDim.x) {
        float4 v = *(const float4*)&xp[i * 4];
        s  += v.x + v.y + v.z + v.w;
        s2 += v.x * v.x + v.y * v.y + v.z * v.z + v.w * v.w;
    }
    __shared__ float rs[32], rs2[32];
    for (int o = 16; o; o >>= 1) {
        s  += __shfl_xor_sync(0xffffffffu, s,  o);
        s2 += __shfl_xor_sync(0xffffffffu, s2, o);
    }
    if ((t & 31) == 0) { rs[t >> 5] = s; rs2[t >> 5] = s2; }
    __syncthreads();
    if (t < 32) {
        int nw = blockDim.x >> 5;
        float a  = (t < nw) ? rs[t]  : 0.f;
        float a2 = (t < nw) ? rs2[t] : 0.f;
        for (int o = 16; o; o >>= 1) {
            a  += __shfl_xor_sync(0xffffffffu, a,  o);
            a2 += __shfl_xor_sync(0xffffffffu, a2, o);
        }
        if (t == 0) {
            float mean = a / (float)GSIZE;
            float var  = a2 / (float)GSIZE - mean * mean;
            rs[0]  = mean;
            rs2[0] = rsqrtf(var + EPSV);
        }
    }
    __syncthreads();
    float mean = rs[0], rstd = rs2[0];
    int c0 = (bg % NGROUPS) * (CC / NGROUPS);
    for (int i = t; i < GSIZE / 4; i += blockDim.x) {
        int c = c0 + (i * 4) / NN;
        float sc = rstd * w[c], bc = bch[c] - mean * sc;
        float4 v = *(const float4*)&xp[i * 4];
        v.x = v.x * sc + bc; v.y = v.y * sc + bc;
        v.z = v.z * sc + bc; v.w = v.w * sc + bc;
        *(float4*)&op[i * 4] = v;
    }
}

// ---------------- pipelined tf32 GEMM with ldmatrix A-frags ----------------
#define BK 32
#define LDA_S 36    // 144 B row stride: 16B-aligned, conflict-free for ldsm
#define LDB_S 132
#define GEMM_STG (128 * LDA_S + BK * LDB_S)          // 8832 floats
#define GEMM_SMEM (2 * GEMM_STG * 4)                 // 70656 B

__global__ __launch_bounds__(256, 2)
void mma_gemm(const float* __restrict__ A,
              const float* __restrict__ Bm,
              float* __restrict__ Cm,
              int K, int lda, int ldb, int ldc,
              long long sBi, long long sCi,
              const float* __restrict__ bias,
              const float* __restrict__ res,
              long long sRi) {
    int z = blockIdx.z;
    Bm += z * sBi;
    Cm += z * sCi;
    if (res) res += z * sRi;

    extern __shared__ float smf[];
    float* As[2] = { smf,               smf + GEMM_STG };
    float* Bs[2] = { smf + 128 * LDA_S, smf + GEMM_STG + 128 * LDA_S };

    const int t  = threadIdx.x;
    const int w  = t >> 5, ln = t & 31;
    const int wr = w >> 2, wc = w & 3;
    const int i0 = blockIdx.x * 128, j0 = blockIdx.y * 128;

    // ldmatrix lane-address components for A
    const int lrow = ln & 15;              // row within 16-row frag block
    const int lcol = (ln >> 4) << 2;       // 0 or 4 (k half)

    auto load_stage = [&](int st, int k0) {
        float* Ad = As[st];
        float* Bd = Bs[st];
#pragma unroll
        for (int r4 = 0; r4 < 4; r4++) {
            int idx = t + 256 * r4;
            int row = idx >> 3, kq = (idx & 7) * 4;
            cp16(&Ad[row * LDA_S + kq], &A[(size_t)(i0 + row) * lda + k0 + kq]);
        }
#pragma unroll
        for (int r4 = 0; r4 < 4; r4++) {
            int idx = t + 256 * r4;
            int k = idx >> 5, jq = (idx & 31) * 4;
            cp16(&Bd[k * LDB_S + jq], &Bm[(size_t)(k0 + k) * ldb + j0 + jq]);
        }
    };

    float acc[4][4][4];
#pragma unroll
    for (int a = 0; a < 4; a++)
#pragma unroll
        for (int b = 0; b < 4; b++)
#pragma unroll
            for (int c = 0; c < 4; c++) acc[a][b][c] = 0.f;

    const int nIter = K / BK;
    load_stage(0, 0);
    cp_commit();

    for (int it = 0; it < nIter; it++) {
        if (it + 1 < nIter) {
            load_stage((it + 1) & 1, (it + 1) * BK);
            cp_commit();
            cp_wait<1>();
        } else {
            cp_wait<0>();
        }
        __syncthreads();
        const unsigned* Ac = (const unsigned*)As[it & 1];
        const unsigned* Bc = (const unsigned*)Bs[it & 1];

#pragma unroll
        for (int ks = 0; ks < 4; ks++) {
            int kk = ks * 8;
            unsigned bf[4][2];
#pragma unroll
            for (int ni = 0; ni < 4; ni++) {
                int nB = wc * 32 + ni * 8 + (ln >> 2);
                int kb = kk + (ln & 3);
                bf[ni][0] = Bc[kb * LDB_S + nB];
                bf[ni][1] = Bc[(kb + 4) * LDB_S + nB];
            }
#pragma unroll
            for (int mi = 0; mi < 4; mi++) {
                unsigned a0, a1, a2, a3;
                ldsm_x4(a0, a1, a2, a3,
                        &Ac[(wr * 64 + mi * 16 + lrow) * LDA_S + kk + lcol]);
#pragma unroll
                for (int ni = 0; ni < 4; ni++)
                    mma_tf32(acc[mi][ni][0], acc[mi][ni][1], acc[mi][ni][2], acc[mi][ni][3],
                             a0, a1, a2, a3, bf[ni][0], bf[ni][1]);
            }
        }
        __syncthreads();
    }

#pragma unroll
    for (int mi = 0; mi < 4; mi++) {
        int r0 = i0 + wr * 64 + mi * 16 + (ln >> 2);
        int r1 = r0 + 8;
        float bv0 = bias ? bias[r0] : 0.f;
        float bv1 = bias ? bias[r1] : 0.f;
#pragma unroll
        for (int ni = 0; ni < 4; ni++) {
            int c0 = j0 + wc * 32 + ni * 8 + 2 * (ln & 3);
            float v00 = acc[mi][ni][0] + bv0;
            float v01 = acc[mi][ni][1] + bv0;
            float v10 = acc[mi][ni][2] + bv1;
            float v11 = acc[mi][ni][3] + bv1;
            if (res) {
                float2 r0v = *(const float2*)&res[(size_t)r0 * ldc + c0];
                float2 r1v = *(const float2*)&res[(size_t)r1 * ldc + c0];
                v00 += r0v.x; v01 += r0v.y;
                v10 += r1v.x; v11 += r1v.y;
            }
            *(float2*)&Cm[(size_t)r0 * ldc + c0] = make_float2(v00, v01);
            *(float2*)&Cm[(size_t)r1 * ldc + c0] = make_float2(v10, v11);
        }
    }
}

// ---------------- fused flash attention: ldmatrix + cp.async K/V pipeline ----------------
#define QT 128
#define MT 64
#define QS_LD 68   // 272 B rows: 16B-aligned, conflict-free
#define KS_LD 72
#define VS_LD 68
#define FA_Q (QT * QS_LD)                       // 8704 words
#define FA_K (HD * KS_LD)                       // 4608 words
#define FA_V (HD * VS_LD)                       // 4352 words
#define FA_SMEM ((FA_Q + 2 * (FA_K + FA_V)) * 4)  // 106496 B

__global__ __launch_bounds__(256, 2)
void flash_attn(const float* __restrict__ qkv, float* __restrict__ ao) {
    extern __shared__ unsigned sm[];
    unsigned* Qs = sm;
    unsigned* Ks[2] = { sm + FA_Q,            sm + FA_Q + FA_K };
    unsigned* Vs[2] = { sm + FA_Q + 2 * FA_K, sm + FA_Q + 2 * FA_K + FA_V };

    const int t = threadIdx.x;
    const int w = t >> 5, ln = t & 31;
    const int r = ln >> 2, j = ln & 3;
    const int bh = blockIdx.y;
    const int b = bh >> 3, h = bh & 7;
    const int q0 = blockIdx.x * QT;

    const float* Qp = qkv + (size_t)b * 3 * CC * NN + (size_t)h * HD * NN;
    const float* Kp = Qp + (size_t)CC * NN;
    const float* Vp = Qp + 2 * (size_t)CC * NN;

    auto load_kv = [&](int st, int mo) {
#pragma unroll
        for (int r4 = 0; r4 < 4; r4++) {
            int idx = t + 256 * r4;
            int c = idx >> 4, mq = (idx & 15) * 4;
            cp16(&Ks[st][c * KS_LD + mq], &Kp[(size_t)c * NN + mo + mq]);
            cp16(&Vs[st][c * VS_LD + mq], &Vp[(size_t)c * NN + mo + mq]);
        }
    };

    load_kv(0, 0);
    cp_commit();

    // Q tile -> Qs[q][c] (raw f32 bits), overlapped with first K/V cp.async
    for (int idx = t; idx < QT * HD; idx += 256) {
        int q = idx & (QT - 1), c = idx >> 7;
        Qs[q * QS_LD + c] = __float_as_uint(Qp[(size_t)c * NN + q0 + q]);
    }

    float o[8][4];
#pragma unroll
    for (int a = 0; a < 8; a++)
#pragma unroll
        for (int bq = 0; bq < 4; bq++) o[a][bq] = 0.f;
    float m0v = -CUDART_INF_F, m1v = -CUDART_INF_F;
    float l0 = 0.f, l1 = 0.f;

    const int src0 = (ln & ~3) | (j >> 1);
    const int src1 = src0 + 2;
    const int lrow = ln & 15;
    const int lcol = (ln >> 4) << 2;
    // V-ldmatrix lane addressing: per pair g of n-blocks
    const int vrow = ((ln >> 4) & 1) * 8 + (ln & 7);   // + g*16
    const int vcol = ((ln >> 3) & 1) << 2;             // + km*8
    const int nIt = NN / MT;

    for (int it = 0; it < nIt; it++) {
        if (it + 1 < nIt) {
            load_kv((it + 1) & 1, (it + 1) * MT);
            cp_commit();
            cp_wait<1>();
        } else {
            cp_wait<0>();
        }
        __syncthreads();
        const unsigned* Kc = Ks[it & 1];
        const unsigned* Vc = Vs[it & 1];

        // ---- S = Q^T K ----
        float s[8][4];
#pragma unroll
        for (int a = 0; a < 8; a++)
#pragma unroll
            for (int bq = 0; bq < 4; bq++) s[a][bq] = 0.f;

#pragma unroll
        for (int kf = 0; kf < 8; kf++) {
            unsigned a0, a1, a2, a3;
            ldsm_x4(a0, a1, a2, a3, &Qs[(w * 16 + lrow) * QS_LD + kf * 8 + lcol]);
            int ca = kf * 8 + j;
#pragma unroll
            for (int ni = 0; ni < 8; ni++) {
                unsigned b0 = Kc[ca * KS_LD + ni * 8 + r];
                unsigned b1 = Kc[(ca + 4) * KS_LD + ni * 8 + r];
                mma_tf32(s[ni][0], s[ni][1], s[ni][2], s[ni][3], a0, a1, a2, a3, b0, b1);
            }
        }

        // ---- online softmax ----
        float tm0 = -CUDART_INF_F, tm1 = -CUDART_INF_F;
#pragma unroll
        for (int ni = 0; ni < 8; ni++) {
            s[ni][0] *= 0.125f; s[ni][1] *= 0.125f;
            s[ni][2] *= 0.125f; s[ni][3] *= 0.125f;
            tm0 = fmaxf(tm0, fmaxf(s[ni][0], s[ni][1]));
            tm1 = fmaxf(tm1, fmaxf(s[ni][2], s[ni][3]));
        }
        tm0 = fmaxf(tm0, __shfl_xor_sync(0xffffffffu, tm0, 1));
        tm0 = fmaxf(tm0, __shfl_xor_sync(0xffffffffu, tm0, 2));
        tm1 = fmaxf(tm1, __shfl_xor_sync(0xffffffffu, tm1, 1));
        tm1 = fmaxf(tm1, __shfl_xor_sync(0xffffffffu, tm1, 2));

        float mn0 = fmaxf(m0v, tm0), mn1 = fmaxf(m1v, tm1);
        float al0 = __expf(m0v - mn0), al1 = __expf(m1v - mn1);
        m0v = mn0; m1v = mn1;

        float rs0 = 0.f, rs1 = 0.f;
#pragma unroll
        for (int ni = 0; ni < 8; ni++) {
            s[ni][0] = __expf(s[ni][0] - mn0);
            s[ni][1] = __expf(s[ni][1] - mn0);
            s[ni][2] = __expf(s[ni][2] - mn1);
            s[ni][3] = __expf(s[ni][3] - mn1);
            rs0 += s[ni][0] + s[ni][1];
            rs1 += s[ni][2] + s[ni][3];
        }
        rs0 += __shfl_xor_sync(0xffffffffu, rs0, 1);
        rs0 += __shfl_xor_sync(0xffffffffu, rs0, 2);
        rs1 += __shfl_xor_sync(0xffffffffu, rs1, 1);
        rs1 += __shfl_xor_sync(0xffffffffu, rs1, 2);
        l0 = l0 * al0 + rs0;
        l1 = l1 * al1 + rs1;

#pragma unroll
        for (int no = 0; no < 8; no++) {
            o[no][0] *= al0; o[no][1] *= al0;
            o[no][2] *= al1; o[no][3] *= al1;
        }

        // ---- O += P * V^T : shuffled P A-frags, ldmatrix V B-frags ----
#pragma unroll
        for (int km = 0; km < 8; km++) {
            float q00 = __shfl_sync(0xffffffffu, s[km][0], src0);
            float q01 = __shfl_sync(0xffffffffu, s[km][1], src0);
            float q10 = __shfl_sync(0xffffffffu, s[km][0], src1);
            float q11 = __shfl_sync(0xffffffffu, s[km][1], src1);
            float q20 = __shfl_sync(0xffffffffu, s[km][2], src0);
            float q21 = __shfl_sync(0xffffffffu, s[km][3], src0);
            float q30 = __shfl_sync(0xffffffffu, s[km][2], src1);
            float q31 = __shfl_sync(0xffffffffu, s[km][3], src1);
            unsigned pa0 = __float_as_uint((j & 1) ? q01 : q00);
            unsigned pa2 = __float_as_uint((j & 1) ? q11 : q10);
            unsigned pa1 = __float_as_uint((j & 1) ? q21 : q20);
            unsigned pa3 = __float_as_uint((j & 1) ? q31 : q30);
#pragma unroll
            for (int g = 0; g < 4; g++) {
                unsigned d0, d1, d2, d3;
                ldsm_x4(d0, d1, d2, d3,
                        &Vc[(g * 16 + vrow) * VS_LD + km * 8 + vcol]);
                mma_tf32(o[g*2][0], o[g*2][1], o[g*2][2], o[g*2][3],
                         pa0, pa1, pa2, pa3, d0, d1);
                mma_tf32(o[g*2+1][0], o[g*2+1][1], o[g*2+1][2], o[g*2+1][3],
                         pa0, pa1, pa2, pa3, d2, d3);
            }
        }
        __syncthreads();
    }

    // ---- epilogue ----
    float inv0 = 1.f / l0, inv1 = 1.f / l1;
    float* aop = ao + (size_t)b * CC * NN + (size_t)h * HD * NN;
    const int qrow = w * 16 + r;
#pragma unroll
    for (int no = 0; no < 8; no++) {
        int hd0 = no * 8 + 2 * j;
        aop[(size_t)hd0 * NN + q0 + qrow]           = o[no][0] * inv0;
        aop[(size_t)(hd0 + 1) * NN + q0 + qrow]     = o[no][1] * inv0;
        aop[(size_t)hd0 * NN + q0 + qrow + 8]       = o[no][2] * inv1;
        aop[(size_t)(hd0 + 1) * NN + q0 + qrow + 8] = o[no][3] * inv1;
    }
}

// ---------------- launch ----------------
extern "C" void kernel_launch(void* const* d_in, const int* in_sizes, int n_in,
                              void* d_out, int out_size) {
    (void)in_sizes; (void)n_in; (void)out_size;
    const float* x  = (const float*)d_in[0];
    const float* nw = (const float*)d_in[1];
    const float* nb = (const float*)d_in[2];
    const float* qw = (const float*)d_in[3];
    const float* qb = (const float*)d_in[4];
    const float* pw = (const float*)d_in[5];
    const float* pb = (const float*)d_in[6];
    float* out = (float*)d_out;

    float *xn, *qkv, *ao;
    cudaGetSymbolAddress((void**)&xn,  g_xn);
    cudaGetSymbolAddress((void**)&qkv, g_qkv);
    cudaGetSymbolAddress((void**)&ao,  g_ao);

    const long long bCN  = (long long)CC * NN;
    const long long b3CN = 3LL * CC * NN;

    cudaFuncSetAttribute(mma_gemm,   cudaFuncAttributeMaxDynamicSharedMemorySize, GEMM_SMEM);
    cudaFuncSetAttribute(flash_attn, cudaFuncAttributeMaxDynamicSharedMemorySize, FA_SMEM);

    // 1) GroupNorm
    groupnorm_kernel<<<BB * NGROUPS, 256>>>(x, nw, nb, xn);

    // 2) QKV
    mma_gemm<<<dim3(12, 8, BB), 256, GEMM_SMEM>>>(
        qw, xn, qkv, CC, CC, NN, NN, bCN, b3CN, qb, nullptr, 0);

    // 3) Fused attention
    flash_attn<<<dim3(NN / QT, BB * NHEADS), 256, FA_SMEM>>>(qkv, ao);

    // 4) Proj + bias + residual
    mma_gemm<<<dim3(4, 8, BB), 256, GEMM_SMEM>>>(
        pw, ao, out, CC, CC, NN, NN, bCN, bCN, pb, x, bCN);
}

// round 10
// speedup vs baseline: 2.5140x; 1.6842x over previous
#include <cuda_runtime.h>
#include <cuda_fp16.h>
#include <cstddef>
#include <cstdint>
#include <math_constants.h>

#define BB 8
#define CC 512
#define NHEADS 8
#define HD 64
#define NN 1024
#define NGROUPS 32
#define GSIZE ((CC / NGROUPS) * NN)   // 16384
#define EPSV 1e-5f

// ---------------- scratch ----------------
__device__ __half g_xn16[BB * CC * NN];        // 8 MB
__device__ __half g_qkv16[BB * 3 * CC * NN];   // 24 MB
__device__ __half g_ao16[BB * CC * NN];        // 8 MB
__device__ __half g_qw16[3 * CC * CC];         // 1.5 MB
__device__ __half g_pw16[CC * CC];             // 0.5 MB

// ---------------- helpers ----------------
__device__ __forceinline__ unsigned smem_u32(const void* p) {
    return (unsigned)__cvta_generic_to_shared(p);
}
__device__ __forceinline__ void cp16(void* sdst, const void* gsrc) {
    asm volatile("cp.async.cg.shared.global [%0], [%1], 16;\n"
                 :: "r"(smem_u32(sdst)), "l"(gsrc));
}
__device__ __forceinline__ void cp_commit() {
    asm volatile("cp.async.commit_group;\n");
}
template <int N>
__device__ __forceinline__ void cp_wait() {
    asm volatile("cp.async.wait_group %0;\n" :: "n"(N));
}
__device__ __forceinline__ void ldsm_x4(unsigned& d0, unsigned& d1,
                                        unsigned& d2, unsigned& d3, const void* p) {
    asm volatile("ldmatrix.sync.aligned.m8n8.x4.shared.b16 {%0,%1,%2,%3}, [%4];\n"
                 : "=r"(d0), "=r"(d1), "=r"(d2), "=r"(d3) : "r"(smem_u32(p)));
}
__device__ __forceinline__ void ldsm_x4t(unsigned& d0, unsigned& d1,
                                         unsigned& d2, unsigned& d3, const void* p) {
    asm volatile("ldmatrix.sync.aligned.m8n8.x4.trans.shared.b16 {%0,%1,%2,%3}, [%4];\n"
                 : "=r"(d0), "=r"(d1), "=r"(d2), "=r"(d3) : "r"(smem_u32(p)));
}
// fp16 MMA m16n8k16, fp32 accum
__device__ __forceinline__ void mma_f16(float& c0, float& c1, float& c2, float& c3,
                                        unsigned a0, unsigned a1, unsigned a2, unsigned a3,
                                        unsigned b0, unsigned b1) {
    asm volatile(
        "mma.sync.aligned.m16n8k16.row.col.f32.f16.f16.f32 "
        "{%0,%1,%2,%3}, {%4,%5,%6,%7}, {%8,%9}, {%0,%1,%2,%3};\n"
        : "+f"(c0), "+f"(c1), "+f"(c2), "+f"(c3)
        : "r"(a0), "r"(a1), "r"(a2), "r"(a3), "r"(b0), "r"(b1));
}
// pack (lo, hi) -> f16x2
__device__ __forceinline__ unsigned packh2(float lo, float hi) {
    unsigned u;
    asm("cvt.rn.f16x2.f32 %0, %2, %1;" : "=r"(u) : "f"(lo), "f"(hi));
    return u;
}

// ---------------- weight f32 -> f16 ----------------
__global__ void convert_fp16(const float* __restrict__ a, __half* __restrict__ b, int n4) {
    int i = blockIdx.x * blockDim.x + threadIdx.x;
    if (i < n4) {
        float4 v = *(const float4*)&a[i * 4];
        __half2* o = (__half2*)&b[i * 4];
        o[0] = __floats2half2_rn(v.x, v.y);
        o[1] = __floats2half2_rn(v.z, v.w);
    }
}

// ---------------- GroupNorm: f32 in -> f16 out ----------------
__global__ void groupnorm_kernel(const float* __restrict__ x,
                                 const float* __restrict__ w,
                                 const float* __restrict__ bch,
                                 __half* __restrict__ xn) {
    int bg = blockIdx.x;
    const float* xp = x + (size_t)bg * GSIZE;
    __half* op = xn + (size_t)bg * GSIZE;
    int t = threadIdx.x;

    float s = 0.f, s2 = 0.f;
    for (int i = t; i < GSIZE / 4; i += blockDim.x) {
        float4 v = *(const float4*)&xp[i * 4];
        s  += v.x + v.y + v.z + v.w;
        s2 += v.x * v.x + v.y * v.y + v.z * v.z + v.w * v.w;
    }
    __shared__ float rs[32], rs2[32];
    for (int o = 16; o; o >>= 1) {
        s  += __shfl_xor_sync(0xffffffffu, s,  o);
        s2 += __shfl_xor_sync(0xffffffffu, s2, o);
    }
    if ((t & 31) == 0) { rs[t >> 5] = s; rs2[t >> 5] = s2; }
    __syncthreads();
    if (t < 32) {
        int nw = blockDim.x >> 5;
        float a  = (t < nw) ? rs[t]  : 0.f;
        float a2 = (t < nw) ? rs2[t] : 0.f;
        for (int o = 16; o; o >>= 1) {
            a  += __shfl_xor_sync(0xffffffffu, a,  o);
            a2 += __shfl_xor_sync(0xffffffffu, a2, o);
        }
        if (t == 0) {
            float mean = a / (float)GSIZE;
            float var  = a2 / (float)GSIZE - mean * mean;
            rs[0]  = mean;
            rs2[0] = rsqrtf(var + EPSV);
        }
    }
    __syncthreads();
    float mean = rs[0], rstd = rs2[0];
    int c0 = (bg % NGROUPS) * (CC / NGROUPS);
    for (int i = t; i < GSIZE / 4; i += blockDim.x) {
        int c = c0 + (i * 4) / NN;
        float sc = rstd * w[c], bc = bch[c] - mean * sc;
        float4 v = *(const float4*)&xp[i * 4];
        __half2* o = (__half2*)&op[i * 4];
        o[0] = __floats2half2_rn(v.x * sc + bc, v.y * sc + bc);
        o[1] = __floats2half2_rn(v.z * sc + bc, v.w * sc + bc);
    }
}

// ---------------- fp16 HGEMM: C[M,N] = A[M,K]*B[K,N] (+bias)(+res) ----------------
// tile 128x128, BK=32, 256 thr (8 warps 2x4), 2-stage cp.async, ldmatrix frags.
#define HA_LD 40                         // fp16 row stride (A: 32 + 8 pad)
#define HB_LD 136                        // fp16 row stride (B: 128 + 8 pad)
#define H_ABYTES (128 * HA_LD * 2)       // 10240
#define H_BBYTES (32 * HB_LD * 2)        // 8704
#define H_STG (H_ABYTES + H_BBYTES)      // 18944
#define H_SMEM (2 * H_STG)               // 37888

template <bool HOUT>
__global__ __launch_bounds__(256, 2)
void hgemm(const __half* __restrict__ A,
           const __half* __restrict__ Bm,
           void* __restrict__ Cv,
           int K, int lda, int ldb, int ldc,
           long long sBi, long long sCi,
           const float* __restrict__ bias,
           const float* __restrict__ res,
           long long sRi) {
    int z = blockIdx.z;
    Bm += z * sBi;
    if (res) res += z * sRi;

    extern __shared__ __align__(16) char smc[];
    const int t  = threadIdx.x;
    const int w  = t >> 5, ln = t & 31;
    const int wr = w >> 2, wc = w & 3;
    const int i0 = blockIdx.x * 128, j0 = blockIdx.y * 128;

    auto load_stage = [&](int st, int k0) {
        char* Ad = smc + st * H_STG;
        char* Bd = Ad + H_ABYTES;
        // A: 128 rows x 32 k fp16 -> 512 chunks of 16B
#pragma unroll
        for (int r = 0; r < 2; r++) {
            int idx = t + 256 * r;
            int row = idx >> 2, kc = idx & 3;
            cp16(Ad + row * (HA_LD * 2) + kc * 16,
                 &A[(size_t)(i0 + row) * lda + k0 + kc * 8]);
        }
        // B: 32 k-rows x 128 n fp16 -> 512 chunks
#pragma unroll
        for (int r = 0; r < 2; r++) {
            int idx = t + 256 * r;
            int k = idx >> 4, nc = idx & 15;
            cp16(Bd + k * (HB_LD * 2) + nc * 16,
                 &Bm[(size_t)(k0 + k) * ldb + j0 + nc * 8]);
        }
    };

    float acc[4][4][4];
#pragma unroll
    for (int a = 0; a < 4; a++)
#pragma unroll
        for (int b = 0; b < 4; b++)
#pragma unroll
            for (int c = 0; c < 4; c++) acc[a][b][c] = 0.f;

    const int nIter = K / 32;
    load_stage(0, 0);
    cp_commit();

    // ldmatrix lane address components
    const int aRow = ln & 15, aCol = (ln >> 4) * 8;                       // A (non-trans)
    const int bRow = (ln & 7) + ((ln >> 4) << 3), bCol8 = ((ln >> 3) & 1) * 8; // B (trans)

    for (int it = 0; it < nIter; it++) {
        if (it + 1 < nIter) {
            load_stage((it + 1) & 1, (it + 1) * 32);
            cp_commit();
            cp_wait<1>();
        } else {
            cp_wait<0>();
        }
        __syncthreads();
        const char* Ac = smc + (it & 1) * H_STG;
        const char* Bc = Ac + H_ABYTES;

#pragma unroll
        for (int ks = 0; ks < 2; ks++) {
            int kk = ks * 16;
            unsigned bf[4][2];
#pragma unroll
            for (int p = 0; p < 2; p++) {
                unsigned r0, r1, r2, r3;
                ldsm_x4t(r0, r1, r2, r3,
                         Bc + ((kk + bRow) * HB_LD + wc * 32 + p * 16 + bCol8) * 2);
                bf[p * 2][0] = r0; bf[p * 2][1] = r2;
                bf[p * 2 + 1][0] = r1; bf[p * 2 + 1][1] = r3;
            }
#pragma unroll
            for (int mi = 0; mi < 4; mi++) {
                unsigned a0, a1, a2, a3;
                ldsm_x4(a0, a1, a2, a3,
                        Ac + ((wr * 64 + mi * 16 + aRow) * HA_LD + kk + aCol) * 2);
#pragma unroll
                for (int ni = 0; ni < 4; ni++)
                    mma_f16(acc[mi][ni][0], acc[mi][ni][1], acc[mi][ni][2], acc[mi][ni][3],
                            a0, a1, a2, a3, bf[ni][0], bf[ni][1]);
            }
        }
        __syncthreads();
    }

    // ---- epilogue ----
#pragma unroll
    for (int mi = 0; mi < 4; mi++) {
        int r0 = i0 + wr * 64 + mi * 16 + (ln >> 2);
        int r1 = r0 + 8;
        float bv0 = bias ? bias[r0] : 0.f;
        float bv1 = bias ? bias[r1] : 0.f;
#pragma unroll
        for (int ni = 0; ni < 4; ni++) {
            int c0 = j0 + wc * 32 + ni * 8 + 2 * (ln & 3);
            float v00 = acc[mi][ni][0] + bv0;
            float v01 = acc[mi][ni][1] + bv0;
            float v10 = acc[mi][ni][2] + bv1;
            float v11 = acc[mi][ni][3] + bv1;
            if (HOUT) {
                __half* Cm = (__half*)Cv + z * sCi;
                *(__half2*)&Cm[(size_t)r0 * ldc + c0] = __floats2half2_rn(v00, v01);
                *(__half2*)&Cm[(size_t)r1 * ldc + c0] = __floats2half2_rn(v10, v11);
            } else {
                float* Cm = (float*)Cv + z * sCi;
                if (res) {
                    float2 r0v = *(const float2*)&res[(size_t)r0 * ldc + c0];
                    float2 r1v = *(const float2*)&res[(size_t)r1 * ldc + c0];
                    v00 += r0v.x; v01 += r0v.y;
                    v10 += r1v.x; v11 += r1v.y;
                }
                *(float2*)&Cm[(size_t)r0 * ldc + c0] = make_float2(v00, v01);
                *(float2*)&Cm[(size_t)r1 * ldc + c0] = make_float2(v10, v11);
            }
        }
    }
}

// ---------------- fused flash attention, fp16 ----------------
// grid (NN/128, BB*NHEADS), 256 thr; Q tile 128 x 64, key tiles 64.
#define QTL 128
#define MTL 64
#define FQ_LD 72                              // fp16 row stride (64+8)
#define FK_LD 72
#define FQ_BYTES (QTL * FQ_LD * 2)            // 18432
#define FK_BYTES (MTL * FK_LD * 2)            // 9216 (c-rows=64)
#define FA_SMEM (FQ_BYTES + 4 * FK_BYTES)     // 55296

__global__ __launch_bounds__(256, 2)
void flash_attn(const __half* __restrict__ qkv, __half* __restrict__ ao) {
    extern __shared__ __align__(16) char smc[];
    __half* Qs = (__half*)smc;
    char* Kst[2] = { smc + FQ_BYTES,                 smc + FQ_BYTES + FK_BYTES };
    char* Vst[2] = { smc + FQ_BYTES + 2 * FK_BYTES,  smc + FQ_BYTES + 3 * FK_BYTES };

    const int t = threadIdx.x;
    const int w = t >> 5, ln = t & 31;
    const int r = ln >> 2, j = ln & 3;
    const int bh = blockIdx.y;
    const int b = bh >> 3, h = bh & 7;
    const int q0 = blockIdx.x * QTL;

    const __half* Qp = qkv + (size_t)b * 3 * CC * NN + (size_t)h * HD * NN;
    const __half* Kp = Qp + (size_t)CC * NN;
    const __half* Vp = Qp + 2 * (size_t)CC * NN;

    auto load_kv = [&](int st, int mo) {
#pragma unroll
        for (int rr = 0; rr < 2; rr++) {
            int idx = t + 256 * rr;          // 0..511
            int c = idx >> 3, mq = idx & 7;
            cp16(Kst[st] + (c * FK_LD + mq * 8) * 2, &Kp[(size_t)c * NN + mo + mq * 8]);
            cp16(Vst[st] + (c * FK_LD + mq * 8) * 2, &Vp[(size_t)c * NN + mo + mq * 8]);
        }
    };

    load_kv(0, 0);
    cp_commit();

    // Q tile -> Qs[q][c], scaled by 0.125 (exact)
    for (int idx = t; idx < QTL * HD; idx += 256) {
        int q = idx & (QTL - 1), c = idx >> 7;
        float f = __half2float(Qp[(size_t)c * NN + q0 + q]) * 0.125f;
        Qs[q * FQ_LD + c] = __float2half_rn(f);
    }

    float o[8][4];
#pragma unroll
    for (int a = 0; a < 8; a++)
#pragma unroll
        for (int bq = 0; bq < 4; bq++) o[a][bq] = 0.f;
    float m0v = -CUDART_INF_F, m1v = -CUDART_INF_F;
    float l0 = 0.f, l1 = 0.f;

    // ldmatrix lane address components
    const int aRow = ln & 15, aCol = (ln >> 4) * 8;                        // Q / V (non-trans)
    const int bRow = (ln & 7) + ((ln >> 4) << 3), bCol8 = ((ln >> 3) & 1) * 8; // K (trans)
    const int nIt = NN / MTL;

    for (int it = 0; it < nIt; it++) {
        if (it + 1 < nIt) {
            load_kv((it + 1) & 1, (it + 1) * MTL);
            cp_commit();
            cp_wait<1>();
        } else {
            cp_wait<0>();
        }
        __syncthreads();
        const char* Kc = Kst[it & 1];
        const char* Vc = Vst[it & 1];

        // ---- S = Q K^T ----
        float s[8][4];
#pragma unroll
        for (int a = 0; a < 8; a++)
#pragma unroll
            for (int bq = 0; bq < 4; bq++) s[a][bq] = 0.f;

#pragma unroll
        for (int kf = 0; kf < 4; kf++) {
            unsigned a0, a1, a2, a3;
            ldsm_x4(a0, a1, a2, a3,
                    (const char*)Qs + ((w * 16 + aRow) * FQ_LD + kf * 16 + aCol) * 2);
#pragma unroll
            for (int mp = 0; mp < 4; mp++) {
                unsigned r0, r1, r2, r3;
                ldsm_x4t(r0, r1, r2, r3,
                         Kc + ((kf * 16 + bRow) * FK_LD + mp * 16 + bCol8) * 2);
                mma_f16(s[2*mp][0], s[2*mp][1], s[2*mp][2], s[2*mp][3],
                        a0, a1, a2, a3, r0, r2);
                mma_f16(s[2*mp+1][0], s[2*mp+1][1], s[2*mp+1][2], s[2*mp+1][3],
                        a0, a1, a2, a3, r1, r3);
            }
        }

        // ---- online softmax (scale pre-folded into Q) ----
        float tm0 = -CUDART_INF_F, tm1 = -CUDART_INF_F;
#pragma unroll
        for (int ni = 0; ni < 8; ni++) {
            tm0 = fmaxf(tm0, fmaxf(s[ni][0], s[ni][1]));
            tm1 = fmaxf(tm1, fmaxf(s[ni][2], s[ni][3]));
        }
        tm0 = fmaxf(tm0, __shfl_xor_sync(0xffffffffu, tm0, 1));
        tm0 = fmaxf(tm0, __shfl_xor_sync(0xffffffffu, tm0, 2));
        tm1 = fmaxf(tm1, __shfl_xor_sync(0xffffffffu, tm1, 1));
        tm1 = fmaxf(tm1, __shfl_xor_sync(0xffffffffu, tm1, 2));

        float mn0 = fmaxf(m0v, tm0), mn1 = fmaxf(m1v, tm1);
        float al0 = __expf(m0v - mn0), al1 = __expf(m1v - mn1);
        m0v = mn0; m1v = mn1;

        float rs0 = 0.f, rs1 = 0.f;
#pragma unroll
        for (int ni = 0; ni < 8; ni++) {
            s[ni][0] = __expf(s[ni][0] - mn0);
            s[ni][1] = __expf(s[ni][1] - mn0);
            s[ni][2] = __expf(s[ni][2] - mn1);
            s[ni][3] = __expf(s[ni][3] - mn1);
            rs0 += s[ni][0] + s[ni][1];
            rs1 += s[ni][2] + s[ni][3];
        }
        rs0 += __shfl_xor_sync(0xffffffffu, rs0, 1);
        rs0 += __shfl_xor_sync(0xffffffffu, rs0, 2);
        rs1 += __shfl_xor_sync(0xffffffffu, rs1, 1);
        rs1 += __shfl_xor_sync(0xffffffffu, rs1, 2);
        l0 = l0 * al0 + rs0;
        l1 = l1 * al1 + rs1;

#pragma unroll
        for (int no = 0; no < 8; no++) {
            o[no][0] *= al0; o[no][1] *= al0;
            o[no][2] *= al1; o[no][3] *= al1;
        }

        // ---- O += P V^T : P C-frag -> A-frag is pure register packing ----
#pragma unroll
        for (int g = 0; g < 4; g++) {
            unsigned pa0 = packh2(s[2*g][0],   s[2*g][1]);
            unsigned pa1 = packh2(s[2*g][2],   s[2*g][3]);
            unsigned pa2 = packh2(s[2*g+1][0], s[2*g+1][1]);
            unsigned pa3 = packh2(s[2*g+1][2], s[2*g+1][3]);
#pragma unroll
            for (int np = 0; np < 4; np++) {
                unsigned r0, r1, r2, r3;
                ldsm_x4(r0, r1, r2, r3,
                        Vc + ((np * 16 + aRow) * FK_LD + g * 16 + aCol) * 2);
                mma_f16(o[2*np][0], o[2*np][1], o[2*np][2], o[2*np][3],
                        pa0, pa1, pa2, pa3, r0, r2);
                mma_f16(o[2*np+1][0], o[2*np+1][1], o[2*np+1][2], o[2*np+1][3],
                        pa0, pa1, pa2, pa3, r1, r3);
            }
        }
        __syncthreads();
    }

    // ---- epilogue: ao fp16 [c][n] ----
    float inv0 = 1.f / l0, inv1 = 1.f / l1;
    __half* aop = ao + (size_t)b * CC * NN + (size_t)h * HD * NN;
    const int qrow = w * 16 + r;
#pragma unroll
    for (int no = 0; no < 8; no++) {
        int hd0 = no * 8 + 2 * j;
        aop[(size_t)hd0 * NN + q0 + qrow]           = __float2half_rn(o[no][0] * inv0);
        aop[(size_t)(hd0 + 1) * NN + q0 + qrow]     = __float2half_rn(o[no][1] * inv0);
        aop[(size_t)hd0 * NN + q0 + qrow + 8]       = __float2half_rn(o[no][2] * inv1);
        aop[(size_t)(hd0 + 1) * NN + q0 + qrow + 8] = __float2half_rn(o[no][3] * inv1);
    }
}

// ---------------- launch ----------------
extern "C" void kernel_launch(void* const* d_in, const int* in_sizes, int n_in,
                              void* d_out, int out_size) {
    (void)in_sizes; (void)n_in; (void)out_size;
    const float* x  = (const float*)d_in[0];
    const float* nw = (const float*)d_in[1];
    const float* nb = (const float*)d_in[2];
    const float* qw = (const float*)d_in[3];
    const float* qb = (const float*)d_in[4];
    const float* pw = (const float*)d_in[5];
    const float* pb = (const float*)d_in[6];
    float* out = (float*)d_out;

    __half *xn16, *qkv16, *ao16, *qw16, *pw16;
    cudaGetSymbolAddress((void**)&xn16,  g_xn16);
    cudaGetSymbolAddress((void**)&qkv16, g_qkv16);
    cudaGetSymbolAddress((void**)&ao16,  g_ao16);
    cudaGetSymbolAddress((void**)&qw16,  g_qw16);
    cudaGetSymbolAddress((void**)&pw16,  g_pw16);

    const long long bCN  = (long long)CC * NN;
    const long long b3CN = 3LL * CC * NN;

    cudaFuncSetAttribute(flash_attn, cudaFuncAttributeMaxDynamicSharedMemorySize, FA_SMEM);

    // 0) weights f32 -> f16
    convert_fp16<<<(3 * CC * CC / 4 + 255) / 256, 256>>>(qw, qw16, 3 * CC * CC / 4);
    convert_fp16<<<(CC * CC / 4 + 255) / 256, 256>>>(pw, pw16, CC * CC / 4);

    // 1) GroupNorm -> fp16 xn
    groupnorm_kernel<<<BB * NGROUPS, 256>>>(x, nw, nb, xn16);

    // 2) QKV (fp16 out): qkv[b] = qkv_w * xn[b] + qkv_b
    hgemm<true><<<dim3(12, 8, BB), 256, H_SMEM>>>(
        qw16, xn16, qkv16, CC, CC, NN, NN, bCN, b3CN, qb, nullptr, 0);

    // 3) Fused attention (fp16 in/out)
    flash_attn<<<dim3(NN / QTL, BB * NHEADS), 256, FA_SMEM>>>(qkv16, ao16);

    // 4) Proj + bias + residual (f32 out)
    hgemm<false><<<dim3(4, 8, BB), 256, H_SMEM>>>(
        pw16, ao16, out, CC, CC, NN, NN, bCN, bCN, pb, x, bCN);
}

// round 11
// speedup vs baseline: 2.6732x; 1.0633x over previous
#include <cuda_runtime.h>
#include <cuda_fp16.h>
#include <cstddef>
#include <cstdint>
#include <math_constants.h>

#define BB 8
#define CC 512
#define NHEADS 8
#define HD 64
#define NN 1024
#define NGROUPS 32
#define GSIZE ((CC / NGROUPS) * NN)   // 16384
#define EPSV 1e-5f

// ---------------- scratch ----------------
__device__ __half g_xn16[BB * CC * NN];        // 8 MB
__device__ __half g_qkv16[BB * 3 * CC * NN];   // 24 MB
__device__ __half g_ao16[BB * CC * NN];        // 8 MB
__device__ __half g_qw16[3 * CC * CC];         // 1.5 MB
__device__ __half g_pw16[CC * CC];             // 0.5 MB

// ---------------- helpers ----------------
__device__ __forceinline__ unsigned smem_u32(const void* p) {
    return (unsigned)__cvta_generic_to_shared(p);
}
__device__ __forceinline__ void cp16(void* sdst, const void* gsrc) {
    asm volatile("cp.async.cg.shared.global [%0], [%1], 16;\n"
                 :: "r"(smem_u32(sdst)), "l"(gsrc));
}
__device__ __forceinline__ void cp_commit() {
    asm volatile("cp.async.commit_group;\n");
}
template <int N>
__device__ __forceinline__ void cp_wait() {
    asm volatile("cp.async.wait_group %0;\n" :: "n"(N));
}
__device__ __forceinline__ void ldsm_x4(unsigned& d0, unsigned& d1,
                                        unsigned& d2, unsigned& d3, const void* p) {
    asm volatile("ldmatrix.sync.aligned.m8n8.x4.shared.b16 {%0,%1,%2,%3}, [%4];\n"
                 : "=r"(d0), "=r"(d1), "=r"(d2), "=r"(d3) : "r"(smem_u32(p)));
}
__device__ __forceinline__ void ldsm_x4t(unsigned& d0, unsigned& d1,
                                         unsigned& d2, unsigned& d3, const void* p) {
    asm volatile("ldmatrix.sync.aligned.m8n8.x4.trans.shared.b16 {%0,%1,%2,%3}, [%4];\n"
                 : "=r"(d0), "=r"(d1), "=r"(d2), "=r"(d3) : "r"(smem_u32(p)));
}
__device__ __forceinline__ void mma_f16(float& c0, float& c1, float& c2, float& c3,
                                        unsigned a0, unsigned a1, unsigned a2, unsigned a3,
                                        unsigned b0, unsigned b1) {
    asm volatile(
        "mma.sync.aligned.m16n8k16.row.col.f32.f16.f16.f32 "
        "{%0,%1,%2,%3}, {%4,%5,%6,%7}, {%8,%9}, {%0,%1,%2,%3};\n"
        : "+f"(c0), "+f"(c1), "+f"(c2), "+f"(c3)
        : "r"(a0), "r"(a1), "r"(a2), "r"(a3), "r"(b0), "r"(b1));
}
__device__ __forceinline__ unsigned packh2(float lo, float hi) {
    unsigned u;
    asm("cvt.rn.f16x2.f32 %0, %2, %1;" : "=r"(u) : "f"(lo), "f"(hi));
    return u;
}

// ---------------- weights f32 -> f16 (both in one launch) ----------------
#define QW4 (3 * CC * CC / 4)
#define PW4 (CC * CC / 4)
__global__ void convert_weights(const float* __restrict__ qw, const float* __restrict__ pw,
                                __half* __restrict__ qw16, __half* __restrict__ pw16) {
    int i = blockIdx.x * blockDim.x + threadIdx.x;
    const float* src;
    __half* dst;
    int k;
    if (i < QW4) { src = qw; dst = qw16; k = i; }
    else if (i < QW4 + PW4) { src = pw; dst = pw16; k = i - QW4; }
    else return;
    float4 v = *(const float4*)&src[k * 4];
    __half2* o = (__half2*)&dst[k * 4];
    o[0] = __floats2half2_rn(v.x, v.y);
    o[1] = __floats2half2_rn(v.z, v.w);
}

// ---------------- GroupNorm: f32 in -> f16 out (512 thr) ----------------
__global__ void groupnorm_kernel(const float* __restrict__ x,
                                 const float* __restrict__ w,
                                 const float* __restrict__ bch,
                                 __half* __restrict__ xn) {
    int bg = blockIdx.x;
    const float* xp = x + (size_t)bg * GSIZE;
    __half* op = xn + (size_t)bg * GSIZE;
    int t = threadIdx.x;

    float s = 0.f, s2 = 0.f;
    for (int i = t; i < GSIZE / 4; i += blockDim.x) {
        float4 v = *(const float4*)&xp[i * 4];
        s  += v.x + v.y + v.z + v.w;
        s2 += v.x * v.x + v.y * v.y + v.z * v.z + v.w * v.w;
    }
    __shared__ float rs[32], rs2[32];
    for (int o = 16; o; o >>= 1) {
        s  += __shfl_xor_sync(0xffffffffu, s,  o);
        s2 += __shfl_xor_sync(0xffffffffu, s2, o);
    }
    if ((t & 31) == 0) { rs[t >> 5] = s; rs2[t >> 5] = s2; }
    __syncthreads();
    if (t < 32) {
        int nw = blockDim.x >> 5;
        float a  = (t < nw) ? rs[t]  : 0.f;
        float a2 = (t < nw) ? rs2[t] : 0.f;
        for (int o = 16; o; o >>= 1) {
            a  += __shfl_xor_sync(0xffffffffu, a,  o);
            a2 += __shfl_xor_sync(0xffffffffu, a2, o);
        }
        if (t == 0) {
            float mean = a / (float)GSIZE;
            float var  = a2 / (float)GSIZE - mean * mean;
            rs[0]  = mean;
            rs2[0] = rsqrtf(var + EPSV);
        }
    }
    __syncthreads();
    float mean = rs[0], rstd = rs2[0];
    int c0 = (bg % NGROUPS) * (CC / NGROUPS);
    for (int i = t; i < GSIZE / 4; i += blockDim.x) {
        int c = c0 + (i * 4) / NN;
        float sc = rstd * w[c], bc = bch[c] - mean * sc;
        float4 v = *(const float4*)&xp[i * 4];
        __half2* o = (__half2*)&op[i * 4];
        o[0] = __floats2half2_rn(v.x * sc + bc, v.y * sc + bc);
        o[1] = __floats2half2_rn(v.z * sc + bc, v.w * sc + bc);
    }
}

// ---------------- fp16 HGEMM, BK=64, 2-stage, one sync/iter ----------------
#define HBK 64
#define HA_LD 72                         // fp16 row stride (64 + 8)
#define HB_LD 136                        // fp16 row stride (128 + 8)
#define H_ABYTES (128 * HA_LD * 2)       // 18432
#define H_BBYTES (HBK * HB_LD * 2)       // 17408
#define H_STG (H_ABYTES + H_BBYTES)      // 35840
#define H_SMEM (2 * H_STG)               // 71680

template <bool HOUT>
__global__ __launch_bounds__(256, 2)
void hgemm(const __half* __restrict__ A,
           const __half* __restrict__ Bm,
           void* __restrict__ Cv,
           int K, int lda, int ldb, int ldc,
           long long sBi, long long sCi,
           const float* __restrict__ bias,
           const float* __restrict__ res,
           long long sRi) {
    int z = blockIdx.z;
    Bm += z * sBi;
    if (res) res += z * sRi;

    extern __shared__ __align__(16) char smc[];
    const int t  = threadIdx.x;
    const int w  = t >> 5, ln = t & 31;
    const int wr = w >> 2, wc = w & 3;
    const int i0 = blockIdx.x * 128, j0 = blockIdx.y * 128;

    auto load_stage = [&](int st, int k0) {
        char* Ad = smc + st * H_STG;
        char* Bd = Ad + H_ABYTES;
        // A: 128 rows x 64 k fp16 = 1024 x 16B chunks
#pragma unroll
        for (int r = 0; r < 4; r++) {
            int idx = t + 256 * r;
            int row = idx >> 3, kc = idx & 7;
            cp16(Ad + row * (HA_LD * 2) + kc * 16,
                 &A[(size_t)(i0 + row) * lda + k0 + kc * 8]);
        }
        // B: 64 k-rows x 128 n fp16 = 1024 x 16B chunks
#pragma unroll
        for (int r = 0; r < 4; r++) {
            int idx = t + 256 * r;
            int k = idx >> 4, nc = idx & 15;
            cp16(Bd + k * (HB_LD * 2) + nc * 16,
                 &Bm[(size_t)(k0 + k) * ldb + j0 + nc * 8]);
        }
    };

    float acc[4][4][4];
#pragma unroll
    for (int a = 0; a < 4; a++)
#pragma unroll
        for (int b = 0; b < 4; b++)
#pragma unroll
            for (int c = 0; c < 4; c++) acc[a][b][c] = 0.f;

    const int nIter = K / HBK;
    load_stage(0, 0);
    cp_commit();

    const int aRow = ln & 15, aCol = (ln >> 4) * 8;
    const int bRow = (ln & 7) + ((ln >> 4) << 3), bCol8 = ((ln >> 3) & 1) * 8;

    for (int it = 0; it < nIter; it++) {
        cp_wait<0>();
        __syncthreads();
        if (it + 1 < nIter) load_stage((it + 1) & 1, (it + 1) * HBK);
        cp_commit();

        const char* Ac = smc + (it & 1) * H_STG;
        const char* Bc = Ac + H_ABYTES;

#pragma unroll
        for (int ks = 0; ks < 4; ks++) {
            int kk = ks * 16;
            unsigned bf[4][2];
#pragma unroll
            for (int p = 0; p < 2; p++) {
                unsigned r0, r1, r2, r3;
                ldsm_x4t(r0, r1, r2, r3,
                         Bc + ((kk + bRow) * HB_LD + wc * 32 + p * 16 + bCol8) * 2);
                bf[p * 2][0] = r0; bf[p * 2][1] = r2;
                bf[p * 2 + 1][0] = r1; bf[p * 2 + 1][1] = r3;
            }
#pragma unroll
            for (int mi = 0; mi < 4; mi++) {
                unsigned a0, a1, a2, a3;
                ldsm_x4(a0, a1, a2, a3,
                        Ac + ((wr * 64 + mi * 16 + aRow) * HA_LD + kk + aCol) * 2);
#pragma unroll
                for (int ni = 0; ni < 4; ni++)
                    mma_f16(acc[mi][ni][0], acc[mi][ni][1], acc[mi][ni][2], acc[mi][ni][3],
                            a0, a1, a2, a3, bf[ni][0], bf[ni][1]);
            }
        }
    }

    // ---- epilogue ----
#pragma unroll
    for (int mi = 0; mi < 4; mi++) {
        int r0 = i0 + wr * 64 + mi * 16 + (ln >> 2);
        int r1 = r0 + 8;
        float bv0 = bias ? bias[r0] : 0.f;
        float bv1 = bias ? bias[r1] : 0.f;
#pragma unroll
        for (int ni = 0; ni < 4; ni++) {
            int c0 = j0 + wc * 32 + ni * 8 + 2 * (ln & 3);
            float v00 = acc[mi][ni][0] + bv0;
            float v01 = acc[mi][ni][1] + bv0;
            float v10 = acc[mi][ni][2] + bv1;
            float v11 = acc[mi][ni][3] + bv1;
            if (HOUT) {
                __half* Cm = (__half*)Cv + z * sCi;
                *(__half2*)&Cm[(size_t)r0 * ldc + c0] = __floats2half2_rn(v00, v01);
                *(__half2*)&Cm[(size_t)r1 * ldc + c0] = __floats2half2_rn(v10, v11);
            } else {
                float* Cm = (float*)Cv + z * sCi;
                if (res) {
                    float2 r0v = *(const float2*)&res[(size_t)r0 * ldc + c0];
                    float2 r1v = *(const float2*)&res[(size_t)r1 * ldc + c0];
                    v00 += r0v.x; v01 += r0v.y;
                    v10 += r1v.x; v11 += r1v.y;
                }
                *(float2*)&Cm[(size_t)r0 * ldc + c0] = make_float2(v00, v01);
                *(float2*)&Cm[(size_t)r1 * ldc + c0] = make_float2(v10, v11);
            }
        }
    }
}

// ---------------- fused flash attention, fp16, 3-stage, one sync/iter ----------------
#define QTL 128
#define MTL 64
#define FQ_LD 72
#define FK_LD 72
#define FQ_BYTES (QTL * FQ_LD * 2)            // 18432
#define FK_BYTES (MTL * FK_LD * 2)            // 9216
#define FA_SMEM (FQ_BYTES + 6 * FK_BYTES)     // 73728

__global__ __launch_bounds__(256, 2)
void flash_attn(const __half* __restrict__ qkv, __half* __restrict__ ao) {
    extern __shared__ __align__(16) char smc[];
    __half* Qs = (__half*)smc;
    char* Kst[3] = { smc + FQ_BYTES,
                     smc + FQ_BYTES + 2 * FK_BYTES,
                     smc + FQ_BYTES + 4 * FK_BYTES };
    char* Vst[3] = { smc + FQ_BYTES + FK_BYTES,
                     smc + FQ_BYTES + 3 * FK_BYTES,
                     smc + FQ_BYTES + 5 * FK_BYTES };

    const int t = threadIdx.x;
    const int w = t >> 5, ln = t & 31;
    const int r = ln >> 2, j = ln & 3;
    const int bh = blockIdx.y;
    const int b = bh >> 3, h = bh & 7;
    const int q0 = blockIdx.x * QTL;

    const __half* Qp = qkv + (size_t)b * 3 * CC * NN + (size_t)h * HD * NN;
    const __half* Kp = Qp + (size_t)CC * NN;
    const __half* Vp = Qp + 2 * (size_t)CC * NN;

    auto load_kv = [&](int st, int mo) {
#pragma unroll
        for (int rr = 0; rr < 2; rr++) {
            int idx = t + 256 * rr;
            int c = idx >> 3, mq = idx & 7;
            cp16(Kst[st] + (c * FK_LD + mq * 8) * 2, &Kp[(size_t)c * NN + mo + mq * 8]);
            cp16(Vst[st] + (c * FK_LD + mq * 8) * 2, &Vp[(size_t)c * NN + mo + mq * 8]);
        }
    };

    load_kv(0, 0);
    cp_commit();
    load_kv(1, MTL);
    cp_commit();

    // Q tile -> Qs[q][c], scaled by 0.125 (exact)
    for (int idx = t; idx < QTL * HD; idx += 256) {
        int q = idx & (QTL - 1), c = idx >> 7;
        float f = __half2float(Qp[(size_t)c * NN + q0 + q]) * 0.125f;
        Qs[q * FQ_LD + c] = __float2half_rn(f);
    }

    float o[8][4];
#pragma unroll
    for (int a = 0; a < 8; a++)
#pragma unroll
        for (int bq = 0; bq < 4; bq++) o[a][bq] = 0.f;
    float m0v = -CUDART_INF_F, m1v = -CUDART_INF_F;
    float l0 = 0.f, l1 = 0.f;

    const int aRow = ln & 15, aCol = (ln >> 4) * 8;
    const int bRow = (ln & 7) + ((ln >> 4) << 3), bCol8 = ((ln >> 3) & 1) * 8;
    const int nIt = NN / MTL;

    int stC = 0;   // consume stage
    int stL = 2;   // load stage
    for (int it = 0; it < nIt; it++) {
        cp_wait<1>();
        __syncthreads();
        if (it + 2 < nIt) load_kv(stL, (it + 2) * MTL);
        cp_commit();    // empty group at tail keeps wait<1> accounting correct
        if (++stL == 3) stL = 0;

        const char* Kc = Kst[stC];
        const char* Vc = Vst[stC];
        if (++stC == 3) stC = 0;

        // ---- S = Q K^T ----
        float s[8][4];
#pragma unroll
        for (int a = 0; a < 8; a++)
#pragma unroll
            for (int bq = 0; bq < 4; bq++) s[a][bq] = 0.f;

#pragma unroll
        for (int kf = 0; kf < 4; kf++) {
            unsigned a0, a1, a2, a3;
            ldsm_x4(a0, a1, a2, a3,
                    (const char*)Qs + ((w * 16 + aRow) * FQ_LD + kf * 16 + aCol) * 2);
#pragma unroll
            for (int mp = 0; mp < 4; mp++) {
                unsigned r0, r1, r2, r3;
                ldsm_x4t(r0, r1, r2, r3,
                         Kc + ((kf * 16 + bRow) * FK_LD + mp * 16 + bCol8) * 2);
                mma_f16(s[2*mp][0], s[2*mp][1], s[2*mp][2], s[2*mp][3],
                        a0, a1, a2, a3, r0, r2);
                mma_f16(s[2*mp+1][0], s[2*mp+1][1], s[2*mp+1][2], s[2*mp+1][3],
                        a0, a1, a2, a3, r1, r3);
            }
        }

        // ---- online softmax ----
        float tm0 = -CUDART_INF_F, tm1 = -CUDART_INF_F;
#pragma unroll
        for (int ni = 0; ni < 8; ni++) {
            tm0 = fmaxf(tm0, fmaxf(s[ni][0], s[ni][1]));
            tm1 = fmaxf(tm1, fmaxf(s[ni][2], s[ni][3]));
        }
        tm0 = fmaxf(tm0, __shfl_xor_sync(0xffffffffu, tm0, 1));
        tm0 = fmaxf(tm0, __shfl_xor_sync(0xffffffffu, tm0, 2));
        tm1 = fmaxf(tm1, __shfl_xor_sync(0xffffffffu, tm1, 1));
        tm1 = fmaxf(tm1, __shfl_xor_sync(0xffffffffu, tm1, 2));

        float mn0 = fmaxf(m0v, tm0), mn1 = fmaxf(m1v, tm1);
        float al0 = __expf(m0v - mn0), al1 = __expf(m1v - mn1);
        m0v = mn0; m1v = mn1;

        float rs0 = 0.f, rs1 = 0.f;
#pragma unroll
        for (int ni = 0; ni < 8; ni++) {
            s[ni][0] = __expf(s[ni][0] - mn0);
            s[ni][1] = __expf(s[ni][1] - mn0);
            s[ni][2] = __expf(s[ni][2] - mn1);
            s[ni][3] = __expf(s[ni][3] - mn1);
            rs0 += s[ni][0] + s[ni][1];
            rs1 += s[ni][2] + s[ni][3];
        }
        rs0 += __shfl_xor_sync(0xffffffffu, rs0, 1);
        rs0 += __shfl_xor_sync(0xffffffffu, rs0, 2);
        rs1 += __shfl_xor_sync(0xffffffffu, rs1, 1);
        rs1 += __shfl_xor_sync(0xffffffffu, rs1, 2);
        l0 = l0 * al0 + rs0;
        l1 = l1 * al1 + rs1;

#pragma unroll
        for (int no = 0; no < 8; no++) {
            o[no][0] *= al0; o[no][1] *= al0;
            o[no][2] *= al1; o[no][3] *= al1;
        }

        // ---- O += P V^T ----
#pragma unroll
        for (int g = 0; g < 4; g++) {
            unsigned pa0 = packh2(s[2*g][0],   s[2*g][1]);
            unsigned pa1 = packh2(s[2*g][2],   s[2*g][3]);
            unsigned pa2 = packh2(s[2*g+1][0], s[2*g+1][1]);
            unsigned pa3 = packh2(s[2*g+1][2], s[2*g+1][3]);
#pragma unroll
            for (int np = 0; np < 4; np++) {
                unsigned r0, r1, r2, r3;
                ldsm_x4(r0, r1, r2, r3,
                        Vc + ((np * 16 + aRow) * FK_LD + g * 16 + aCol) * 2);
                mma_f16(o[2*np][0], o[2*np][1], o[2*np][2], o[2*np][3],
                        pa0, pa1, pa2, pa3, r0, r2);
                mma_f16(o[2*np+1][0], o[2*np+1][1], o[2*np+1][2], o[2*np+1][3],
                        pa0, pa1, pa2, pa3, r1, r3);
            }
        }
    }

    // ---- epilogue ----
    float inv0 = 1.f / l0, inv1 = 1.f / l1;
    __half* aop = ao + (size_t)b * CC * NN + (size_t)h * HD * NN;
    const int qrow = w * 16 + r;
#pragma unroll
    for (int no = 0; no < 8; no++) {
        int hd0 = no * 8 + 2 * j;
        aop[(size_t)hd0 * NN + q0 + qrow]           = __float2half_rn(o[no][0] * inv0);
        aop[(size_t)(hd0 + 1) * NN + q0 + qrow]     = __float2half_rn(o[no][1] * inv0);
        aop[(size_t)hd0 * NN + q0 + qrow + 8]       = __float2half_rn(o[no][2] * inv1);
        aop[(size_t)(hd0 + 1) * NN + q0 + qrow + 8] = __float2half_rn(o[no][3] * inv1);
    }
}

// ---------------- launch ----------------
extern "C" void kernel_launch(void* const* d_in, const int* in_sizes, int n_in,
                              void* d_out, int out_size) {
    (void)in_sizes; (void)n_in; (void)out_size;
    const float* x  = (const float*)d_in[0];
    const float* nw = (const float*)d_in[1];
    const float* nb = (const float*)d_in[2];
    const float* qw = (const float*)d_in[3];
    const float* qb = (const float*)d_in[4];
    const float* pw = (const float*)d_in[5];
    const float* pb = (const float*)d_in[6];
    float* out = (float*)d_out;

    __half *xn16, *qkv16, *ao16, *qw16, *pw16;
    cudaGetSymbolAddress((void**)&xn16,  g_xn16);
    cudaGetSymbolAddress((void**)&qkv16, g_qkv16);
    cudaGetSymbolAddress((void**)&ao16,  g_ao16);
    cudaGetSymbolAddress((void**)&qw16,  g_qw16);
    cudaGetSymbolAddress((void**)&pw16,  g_pw16);

    const long long bCN  = (long long)CC * NN;
    const long long b3CN = 3LL * CC * NN;

    cudaFuncSetAttribute(hgemm<true>,  cudaFuncAttributeMaxDynamicSharedMemorySize, H_SMEM);
    cudaFuncSetAttribute(hgemm<false>, cudaFuncAttributeMaxDynamicSharedMemorySize, H_SMEM);
    cudaFuncSetAttribute(flash_attn,   cudaFuncAttributeMaxDynamicSharedMemorySize, FA_SMEM);

    // 0) weights f32 -> f16 (single launch)
    convert_weights<<<(QW4 + PW4 + 255) / 256, 256>>>(qw, pw, qw16, pw16);

    // 1) GroupNorm -> fp16 xn
    groupnorm_kernel<<<BB * NGROUPS, 512>>>(x, nw, nb, xn16);

    // 2) QKV (fp16 out)
    hgemm<true><<<dim3(12, 8, BB), 256, H_SMEM>>>(
        qw16, xn16, qkv16, CC, CC, NN, NN, bCN, b3CN, qb, nullptr, 0);

    // 3) Fused attention (fp16 in/out)
    flash_attn<<<dim3(NN / QTL, BB * NHEADS), 256, FA_SMEM>>>(qkv16, ao16);

    // 4) Proj + bias + residual (f32 out)
    hgemm<false><<<dim3(4, 8, BB), 256, H_SMEM>>>(
        pw16, ao16, out, CC, CC, NN, NN, bCN, bCN, pb, x, bCN);
}

// round 12
// speedup vs baseline: 2.7456x; 1.0271x over previous
#include <cuda_runtime.h>
#include <cuda_fp16.h>
#include <cstddef>
#include <cstdint>
#include <math_constants.h>

#define BB 8
#define CC 512
#define NHEADS 8
#define HD 64
#define NN 1024
#define NGROUPS 32
#define GSIZE ((CC / NGROUPS) * NN)   // 16384
#define EPSV 1e-5f

// ---------------- scratch ----------------
__device__ __half g_xn16[BB * CC * NN];        // 8 MB
__device__ __half g_qkv16[BB * 3 * CC * NN];   // 24 MB
__device__ __half g_ao16[BB * CC * NN];        // 8 MB
__device__ __half g_qw16[3 * CC * CC];         // 1.5 MB
__device__ __half g_pw16[CC * CC];             // 0.5 MB

// ---------------- helpers ----------------
__device__ __forceinline__ unsigned smem_u32(const void* p) {
    return (unsigned)__cvta_generic_to_shared(p);
}
__device__ __forceinline__ void cp16(void* sdst, const void* gsrc) {
    asm volatile("cp.async.cg.shared.global [%0], [%1], 16;\n"
                 :: "r"(smem_u32(sdst)), "l"(gsrc));
}
__device__ __forceinline__ void cp_commit() {
    asm volatile("cp.async.commit_group;\n");
}
template <int N>
__device__ __forceinline__ void cp_wait() {
    asm volatile("cp.async.wait_group %0;\n" :: "n"(N));
}
__device__ __forceinline__ void ldsm_x4(unsigned& d0, unsigned& d1,
                                        unsigned& d2, unsigned& d3, const void* p) {
    asm volatile("ldmatrix.sync.aligned.m8n8.x4.shared.b16 {%0,%1,%2,%3}, [%4];\n"
                 : "=r"(d0), "=r"(d1), "=r"(d2), "=r"(d3) : "r"(smem_u32(p)));
}
__device__ __forceinline__ void ldsm_x4t(unsigned& d0, unsigned& d1,
                                         unsigned& d2, unsigned& d3, const void* p) {
    asm volatile("ldmatrix.sync.aligned.m8n8.x4.trans.shared.b16 {%0,%1,%2,%3}, [%4];\n"
                 : "=r"(d0), "=r"(d1), "=r"(d2), "=r"(d3) : "r"(smem_u32(p)));
}
__device__ __forceinline__ void mma_f16(float& c0, float& c1, float& c2, float& c3,
                                        unsigned a0, unsigned a1, unsigned a2, unsigned a3,
                                        unsigned b0, unsigned b1) {
    asm volatile(
        "mma.sync.aligned.m16n8k16.row.col.f32.f16.f16.f32 "
        "{%0,%1,%2,%3}, {%4,%5,%6,%7}, {%8,%9}, {%0,%1,%2,%3};\n"
        : "+f"(c0), "+f"(c1), "+f"(c2), "+f"(c3)
        : "r"(a0), "r"(a1), "r"(a2), "r"(a3), "r"(b0), "r"(b1));
}
__device__ __forceinline__ unsigned packh2(float lo, float hi) {
    unsigned u;
    asm("cvt.rn.f16x2.f32 %0, %2, %1;" : "=r"(u) : "f"(lo), "f"(hi));
    return u;
}
// 2 exps in one MUFU op
__device__ __forceinline__ unsigned h2exp2(unsigned x) {
    unsigned r;
    asm("ex2.approx.f16x2 %0, %1;" : "=r"(r) : "r"(x));
    return r;
}
__device__ __forceinline__ float h2sum(unsigned x) {
    __half2 h = *(__half2*)&x;
    float2 f = __half22float2(h);
    return f.x + f.y;
}

// ---------------- weights f32 -> f16 ----------------
#define QW4 (3 * CC * CC / 4)
#define PW4 (CC * CC / 4)
__global__ void convert_weights(const float* __restrict__ qw, const float* __restrict__ pw,
                                __half* __restrict__ qw16, __half* __restrict__ pw16) {
    int i = blockIdx.x * blockDim.x + threadIdx.x;
    const float* src;
    __half* dst;
    int k;
    if (i < QW4) { src = qw; dst = qw16; k = i; }
    else if (i < QW4 + PW4) { src = pw; dst = pw16; k = i - QW4; }
    else return;
    float4 v = *(const float4*)&src[k * 4];
    __half2* o = (__half2*)&dst[k * 4];
    o[0] = __floats2half2_rn(v.x, v.y);
    o[1] = __floats2half2_rn(v.z, v.w);
}

// ---------------- GroupNorm: f32 in -> f16 out ----------------
__global__ void groupnorm_kernel(const float* __restrict__ x,
                                 const float* __restrict__ w,
                                 const float* __restrict__ bch,
                                 __half* __restrict__ xn) {
    int bg = blockIdx.x;
    const float* xp = x + (size_t)bg * GSIZE;
    __half* op = xn + (size_t)bg * GSIZE;
    int t = threadIdx.x;

    float s = 0.f, s2 = 0.f;
    for (int i = t; i < GSIZE / 4; i += blockDim.x) {
        float4 v = *(const float4*)&xp[i * 4];
        s  += v.x + v.y + v.z + v.w;
        s2 += v.x * v.x + v.y * v.y + v.z * v.z + v.w * v.w;
    }
    __shared__ float rs[32], rs2[32];
    for (int o = 16; o; o >>= 1) {
        s  += __shfl_xor_sync(0xffffffffu, s,  o);
        s2 += __shfl_xor_sync(0xffffffffu, s2, o);
    }
    if ((t & 31) == 0) { rs[t >> 5] = s; rs2[t >> 5] = s2; }
    __syncthreads();
    if (t < 32) {
        int nw = blockDim.x >> 5;
        float a  = (t < nw) ? rs[t]  : 0.f;
        float a2 = (t < nw) ? rs2[t] : 0.f;
        for (int o = 16; o; o >>= 1) {
            a  += __shfl_xor_sync(0xffffffffu, a,  o);
            a2 += __shfl_xor_sync(0xffffffffu, a2, o);
        }
        if (t == 0) {
            float mean = a / (float)GSIZE;
            float var  = a2 / (float)GSIZE - mean * mean;
            rs[0]  = mean;
            rs2[0] = rsqrtf(var + EPSV);
        }
    }
    __syncthreads();
    float mean = rs[0], rstd = rs2[0];
    int c0 = (bg % NGROUPS) * (CC / NGROUPS);
    for (int i = t; i < GSIZE / 4; i += blockDim.x) {
        int c = c0 + (i * 4) / NN;
        float sc = rstd * w[c], bc = bch[c] - mean * sc;
        float4 v = *(const float4*)&xp[i * 4];
        __half2* o = (__half2*)&op[i * 4];
        o[0] = __floats2half2_rn(v.x * sc + bc, v.y * sc + bc);
        o[1] = __floats2half2_rn(v.z * sc + bc, v.w * sc + bc);
    }
}

// ---------------- fp16 HGEMM, BK=64, 2-stage, one sync/iter ----------------
#define HBK 64
#define HA_LD 72
#define HB_LD 136
#define H_ABYTES (128 * HA_LD * 2)       // 18432
#define H_BBYTES (HBK * HB_LD * 2)       // 17408
#define H_STG (H_ABYTES + H_BBYTES)      // 35840
#define H_SMEM (2 * H_STG)               // 71680

template <bool HOUT>
__global__ __launch_bounds__(256, 2)
void hgemm(const __half* __restrict__ A,
           const __half* __restrict__ Bm,
           void* __restrict__ Cv,
           int K, int lda, int ldb, int ldc,
           long long sBi, long long sCi,
           const float* __restrict__ bias,
           const float* __restrict__ res,
           long long sRi) {
    int z = blockIdx.z;
    Bm += z * sBi;
    if (res) res += z * sRi;

    extern __shared__ __align__(16) char smc[];
    const int t  = threadIdx.x;
    const int w  = t >> 5, ln = t & 31;
    const int wr = w >> 2, wc = w & 3;
    const int i0 = blockIdx.x * 128, j0 = blockIdx.y * 128;

    auto load_stage = [&](int st, int k0) {
        char* Ad = smc + st * H_STG;
        char* Bd = Ad + H_ABYTES;
#pragma unroll
        for (int r = 0; r < 4; r++) {
            int idx = t + 256 * r;
            int row = idx >> 3, kc = idx & 7;
            cp16(Ad + row * (HA_LD * 2) + kc * 16,
                 &A[(size_t)(i0 + row) * lda + k0 + kc * 8]);
        }
#pragma unroll
        for (int r = 0; r < 4; r++) {
            int idx = t + 256 * r;
            int k = idx >> 4, nc = idx & 15;
            cp16(Bd + k * (HB_LD * 2) + nc * 16,
                 &Bm[(size_t)(k0 + k) * ldb + j0 + nc * 8]);
        }
    };

    float acc[4][4][4];
#pragma unroll
    for (int a = 0; a < 4; a++)
#pragma unroll
        for (int b = 0; b < 4; b++)
#pragma unroll
            for (int c = 0; c < 4; c++) acc[a][b][c] = 0.f;

    const int nIter = K / HBK;
    load_stage(0, 0);
    cp_commit();

    const int aRow = ln & 15, aCol = (ln >> 4) * 8;
    const int bRow = (ln & 7) + ((ln >> 4) << 3), bCol8 = ((ln >> 3) & 1) * 8;

    for (int it = 0; it < nIter; it++) {
        cp_wait<0>();
        __syncthreads();
        if (it + 1 < nIter) load_stage((it + 1) & 1, (it + 1) * HBK);
        cp_commit();

        const char* Ac = smc + (it & 1) * H_STG;
        const char* Bc = Ac + H_ABYTES;

#pragma unroll
        for (int ks = 0; ks < 4; ks++) {
            int kk = ks * 16;
            unsigned bf[4][2];
#pragma unroll
            for (int p = 0; p < 2; p++) {
                unsigned r0, r1, r2, r3;
                ldsm_x4t(r0, r1, r2, r3,
                         Bc + ((kk + bRow) * HB_LD + wc * 32 + p * 16 + bCol8) * 2);
                bf[p * 2][0] = r0; bf[p * 2][1] = r2;
                bf[p * 2 + 1][0] = r1; bf[p * 2 + 1][1] = r3;
            }
#pragma unroll
            for (int mi = 0; mi < 4; mi++) {
                unsigned a0, a1, a2, a3;
                ldsm_x4(a0, a1, a2, a3,
                        Ac + ((wr * 64 + mi * 16 + aRow) * HA_LD + kk + aCol) * 2);
#pragma unroll
                for (int ni = 0; ni < 4; ni++)
                    mma_f16(acc[mi][ni][0], acc[mi][ni][1], acc[mi][ni][2], acc[mi][ni][3],
                            a0, a1, a2, a3, bf[ni][0], bf[ni][1]);
            }
        }
    }

    // ---- epilogue ----
#pragma unroll
    for (int mi = 0; mi < 4; mi++) {
        int r0 = i0 + wr * 64 + mi * 16 + (ln >> 2);
        int r1 = r0 + 8;
        float bv0 = bias ? bias[r0] : 0.f;
        float bv1 = bias ? bias[r1] : 0.f;
#pragma unroll
        for (int ni = 0; ni < 4; ni++) {
            int c0 = j0 + wc * 32 + ni * 8 + 2 * (ln & 3);
            float v00 = acc[mi][ni][0] + bv0;
            float v01 = acc[mi][ni][1] + bv0;
            float v10 = acc[mi][ni][2] + bv1;
            float v11 = acc[mi][ni][3] + bv1;
            if (HOUT) {
                __half* Cm = (__half*)Cv + z * sCi;
                *(__half2*)&Cm[(size_t)r0 * ldc + c0] = __floats2half2_rn(v00, v01);
                *(__half2*)&Cm[(size_t)r1 * ldc + c0] = __floats2half2_rn(v10, v11);
            } else {
                float* Cm = (float*)Cv + z * sCi;
                if (res) {
                    float2 r0v = *(const float2*)&res[(size_t)r0 * ldc + c0];
                    float2 r1v = *(const float2*)&res[(size_t)r1 * ldc + c0];
                    v00 += r0v.x; v01 += r0v.y;
                    v10 += r1v.x; v11 += r1v.y;
                }
                *(float2*)&Cm[(size_t)r0 * ldc + c0] = make_float2(v00, v01);
                *(float2*)&Cm[(size_t)r1 * ldc + c0] = make_float2(v10, v11);
            }
        }
    }
}

// ---------------- fused flash attention: log2-domain softmax, f16x2 exp ----------------
#define QTL 128
#define MTL 64
#define FQ_LD 72
#define FK_LD 72
#define FQ_BYTES (QTL * FQ_LD * 2)            // 18432
#define FK_BYTES (MTL * FK_LD * 2)            // 9216
#define FA_SMEM (FQ_BYTES + 6 * FK_BYTES)     // 73728

__global__ __launch_bounds__(256, 2)
void flash_attn(const __half* __restrict__ qkv, __half* __restrict__ ao) {
    extern __shared__ __align__(16) char smc[];
    __half* Qs = (__half*)smc;
    char* Kst[3] = { smc + FQ_BYTES,
                     smc + FQ_BYTES + 2 * FK_BYTES,
                     smc + FQ_BYTES + 4 * FK_BYTES };
    char* Vst[3] = { smc + FQ_BYTES + FK_BYTES,
                     smc + FQ_BYTES + 3 * FK_BYTES,
                     smc + FQ_BYTES + 5 * FK_BYTES };

    const int t = threadIdx.x;
    const int w = t >> 5, ln = t & 31;
    const int r = ln >> 2, j = ln & 3;
    const int bh = blockIdx.y;
    const int b = bh >> 3, h = bh & 7;
    const int q0 = blockIdx.x * QTL;

    const __half* Qp = qkv + (size_t)b * 3 * CC * NN + (size_t)h * HD * NN;
    const __half* Kp = Qp + (size_t)CC * NN;
    const __half* Vp = Qp + 2 * (size_t)CC * NN;

    auto load_kv = [&](int st, int mo) {
#pragma unroll
        for (int rr = 0; rr < 2; rr++) {
            int idx = t + 256 * rr;
            int c = idx >> 3, mq = idx & 7;
            cp16(Kst[st] + (c * FK_LD + mq * 8) * 2, &Kp[(size_t)c * NN + mo + mq * 8]);
            cp16(Vst[st] + (c * FK_LD + mq * 8) * 2, &Vp[(size_t)c * NN + mo + mq * 8]);
        }
    };

    load_kv(0, 0);
    cp_commit();
    load_kv(1, MTL);
    cp_commit();

    // Q tile -> Qs[q][c], scaled by 0.125 * log2(e)  (log2-domain softmax)
    const float QSCALE = 0.125f * 1.44269504f;
    for (int idx = t; idx < QTL * HD; idx += 256) {
        int q = idx & (QTL - 1), c = idx >> 7;
        float f = __half2float(Qp[(size_t)c * NN + q0 + q]) * QSCALE;
        Qs[q * FQ_LD + c] = __float2half_rn(f);
    }

    float o[8][4];
#pragma unroll
    for (int a = 0; a < 8; a++)
#pragma unroll
        for (int bq = 0; bq < 4; bq++) o[a][bq] = 0.f;
    float m0v = -CUDART_INF_F, m1v = -CUDART_INF_F;
    float l0 = 0.f, l1 = 0.f;

    const int aRow = ln & 15, aCol = (ln >> 4) * 8;
    const int bRow = (ln & 7) + ((ln >> 4) << 3), bCol8 = ((ln >> 3) & 1) * 8;
    const int nIt = NN / MTL;

    int stC = 0;
    int stL = 2;
    for (int it = 0; it < nIt; it++) {
        cp_wait<1>();
        __syncthreads();
        if (it + 2 < nIt) load_kv(stL, (it + 2) * MTL);
        cp_commit();
        if (++stL == 3) stL = 0;

        const char* Kc = Kst[stC];
        const char* Vc = Vst[stC];
        if (++stC == 3) stC = 0;

        // ---- S = Q K^T (log2-scaled) ----
        float s[8][4];
#pragma unroll
        for (int a = 0; a < 8; a++)
#pragma unroll
            for (int bq = 0; bq < 4; bq++) s[a][bq] = 0.f;

#pragma unroll
        for (int kf = 0; kf < 4; kf++) {
            unsigned a0, a1, a2, a3;
            ldsm_x4(a0, a1, a2, a3,
                    (const char*)Qs + ((w * 16 + aRow) * FQ_LD + kf * 16 + aCol) * 2);
#pragma unroll
            for (int mp = 0; mp < 4; mp++) {
                unsigned r0, r1, r2, r3;
                ldsm_x4t(r0, r1, r2, r3,
                         Kc + ((kf * 16 + bRow) * FK_LD + mp * 16 + bCol8) * 2);
                mma_f16(s[2*mp][0], s[2*mp][1], s[2*mp][2], s[2*mp][3],
                        a0, a1, a2, a3, r0, r2);
                mma_f16(s[2*mp+1][0], s[2*mp+1][1], s[2*mp+1][2], s[2*mp+1][3],
                        a0, a1, a2, a3, r1, r3);
            }
        }

        // ---- online softmax, log2 domain ----
        float tm0 = -CUDART_INF_F, tm1 = -CUDART_INF_F;
#pragma unroll
        for (int ni = 0; ni < 8; ni++) {
            tm0 = fmaxf(tm0, fmaxf(s[ni][0], s[ni][1]));
            tm1 = fmaxf(tm1, fmaxf(s[ni][2], s[ni][3]));
        }
        tm0 = fmaxf(tm0, __shfl_xor_sync(0xffffffffu, tm0, 1));
        tm0 = fmaxf(tm0, __shfl_xor_sync(0xffffffffu, tm0, 2));
        tm1 = fmaxf(tm1, __shfl_xor_sync(0xffffffffu, tm1, 1));
        tm1 = fmaxf(tm1, __shfl_xor_sync(0xffffffffu, tm1, 2));

        float mn0 = fmaxf(m0v, tm0), mn1 = fmaxf(m1v, tm1);
        float al0 = exp2f(m0v - mn0), al1 = exp2f(m1v - mn1);
        m0v = mn0; m1v = mn1;

        // P = 2^(s - m) computed pairwise in fp16 (one MUFU per 2 elements),
        // emerging already packed as PV A-fragments.
        unsigned pa[4][4];
        float rs0 = 0.f, rs1 = 0.f;
#pragma unroll
        for (int g = 0; g < 4; g++) {
            unsigned p00 = h2exp2(packh2(s[2*g][0]   - mn0, s[2*g][1]   - mn0));
            unsigned p01 = h2exp2(packh2(s[2*g][2]   - mn1, s[2*g][3]   - mn1));
            unsigned p10 = h2exp2(packh2(s[2*g+1][0] - mn0, s[2*g+1][1] - mn0));
            unsigned p11 = h2exp2(packh2(s[2*g+1][2] - mn1, s[2*g+1][3] - mn1));
            pa[g][0] = p00; pa[g][1] = p01; pa[g][2] = p10; pa[g][3] = p11;
            rs0 += h2sum(p00) + h2sum(p10);
            rs1 += h2sum(p01) + h2sum(p11);
        }
        rs0 += __shfl_xor_sync(0xffffffffu, rs0, 1);
        rs0 += __shfl_xor_sync(0xffffffffu, rs0, 2);
        rs1 += __shfl_xor_sync(0xffffffffu, rs1, 1);
        rs1 += __shfl_xor_sync(0xffffffffu, rs1, 2);
        l0 = l0 * al0 + rs0;
        l1 = l1 * al1 + rs1;

#pragma unroll
        for (int no = 0; no < 8; no++) {
            o[no][0] *= al0; o[no][1] *= al0;
            o[no][2] *= al1; o[no][3] *= al1;
        }

        // ---- O += P V^T ----
#pragma unroll
        for (int g = 0; g < 4; g++) {
#pragma unroll
            for (int np = 0; np < 4; np++) {
                unsigned r0, r1, r2, r3;
                ldsm_x4(r0, r1, r2, r3,
                        Vc + ((np * 16 + aRow) * FK_LD + g * 16 + aCol) * 2);
                mma_f16(o[2*np][0], o[2*np][1], o[2*np][2], o[2*np][3],
                        pa[g][0], pa[g][1], pa[g][2], pa[g][3], r0, r2);
                mma_f16(o[2*np+1][0], o[2*np+1][1], o[2*np+1][2], o[2*np+1][3],
                        pa[g][0], pa[g][1], pa[g][2], pa[g][3], r1, r3);
            }
        }
    }

    // ---- epilogue ----
    float inv0 = 1.f / l0, inv1 = 1.f / l1;
    __half* aop = ao + (size_t)b * CC * NN + (size_t)h * HD * NN;
    const int qrow = w * 16 + r;
#pragma unroll
    for (int no = 0; no < 8; no++) {
        int hd0 = no * 8 + 2 * j;
        aop[(size_t)hd0 * NN + q0 + qrow]           = __float2half_rn(o[no][0] * inv0);
        aop[(size_t)(hd0 + 1) * NN + q0 + qrow]     = __float2half_rn(o[no][1] * inv0);
        aop[(size_t)hd0 * NN + q0 + qrow + 8]       = __float2half_rn(o[no][2] * inv1);
        aop[(size_t)(hd0 + 1) * NN + q0 + qrow + 8] = __float2half_rn(o[no][3] * inv1);
    }
}

// ---------------- launch ----------------
extern "C" void kernel_launch(void* const* d_in, const int* in_sizes, int n_in,
                              void* d_out, int out_size) {
    (void)in_sizes; (void)n_in; (void)out_size;
    const float* x  = (const float*)d_in[0];
    const float* nw = (const float*)d_in[1];
    const float* nb = (const float*)d_in[2];
    const float* qw = (const float*)d_in[3];
    const float* qb = (const float*)d_in[4];
    const float* pw = (const float*)d_in[5];
    const float* pb = (const float*)d_in[6];
    float* out = (float*)d_out;

    __half *xn16, *qkv16, *ao16, *qw16, *pw16;
    cudaGetSymbolAddress((void**)&xn16,  g_xn16);
    cudaGetSymbolAddress((void**)&qkv16, g_qkv16);
    cudaGetSymbolAddress((void**)&ao16,  g_ao16);
    cudaGetSymbolAddress((void**)&qw16,  g_qw16);
    cudaGetSymbolAddress((void**)&pw16,  g_pw16);

    const long long bCN  = (long long)CC * NN;
    const long long b3CN = 3LL * CC * NN;

    cudaFuncSetAttribute(hgemm<true>,  cudaFuncAttributeMaxDynamicSharedMemorySize, H_SMEM);
    cudaFuncSetAttribute(hgemm<false>, cudaFuncAttributeMaxDynamicSharedMemorySize, H_SMEM);
    cudaFuncSetAttribute(flash_attn,   cudaFuncAttributeMaxDynamicSharedMemorySize, FA_SMEM);

    // 0) weights f32 -> f16
    convert_weights<<<(QW4 + PW4 + 255) / 256, 256>>>(qw, pw, qw16, pw16);

    // 1) GroupNorm -> fp16 xn
    groupnorm_kernel<<<BB * NGROUPS, 512>>>(x, nw, nb, xn16);

    // 2) QKV (fp16 out)
    hgemm<true><<<dim3(12, 8, BB), 256, H_SMEM>>>(
        qw16, xn16, qkv16, CC, CC, NN, NN, bCN, b3CN, qb, nullptr, 0);

    // 3) Fused attention (fp16 in/out)
    flash_attn<<<dim3(NN / QTL, BB * NHEADS), 256, FA_SMEM>>>(qkv16, ao16);

    // 4) Proj + bias + residual (f32 out)
    hgemm<false><<<dim3(4, 8, BB), 256, H_SMEM>>>(
        pw16, ao16, out, CC, CC, NN, NN, bCN, bCN, pb, x, bCN);
}